// round 6
// baseline (speedup 1.0000x reference)
#include <cuda_runtime.h>
#include <cuda_bf16.h>
#include <cstdint>

// ---------------------------------------------------------------------------
// Problem constants
// ---------------------------------------------------------------------------
#define BATCH   2
#define SEQLEN  1024
#define DMODEL  768
#define DINNER  1536
#define DSTATE  16
#define DTRANK  48
#define XDBL    80          // DTRANK + 2*DSTATE
#define MROWS   (BATCH*SEQLEN)      // 2048

// ---------------------------------------------------------------------------
// Scratch (device globals: no runtime allocation allowed)
// ---------------------------------------------------------------------------
__device__ float g_xz[(size_t)MROWS * 2 * DINNER];        // (2048, 3072)
__device__ float g_xc[2][(size_t)MROWS * DINNER];         // conv+silu out per branch
__device__ float g_xdbl[2][(size_t)MROWS * XDBL];         // dt|B|C per branch
__device__ float g_delta[2][(size_t)MROWS * DINNER];      // softplus(dt_proj)
__device__ float g_y[2][(size_t)MROWS * DINNER];          // scan outputs (branch1 un-flipped)

// packed f32x2 helpers -------------------------------------------------------
__device__ __forceinline__ unsigned long long dupf2(float a) {
    unsigned long long r;
    asm("mov.b64 %0, {%1, %1};" : "=l"(r) : "f"(a));
    return r;
}
#define FMA2(acc, a2, b2) \
    asm("fma.rn.f32x2 %0, %1, %2, %0;" : "+l"(acc) : "l"(a2), "l"(b2))

__device__ __forceinline__ float2 unpack2(unsigned long long v) {
    float2 r;
    asm("mov.b64 {%0, %1}, %2;" : "=f"(r.x), "=f"(r.y) : "l"(v));
    return r;
}

// ---------------------------------------------------------------------------
// K1: 128x128x8 fp32 SGEMM (NT), double-buffered, f32x2 microkernel.
//     C = A @ B^T into g_xz
// ---------------------------------------------------------------------------
__global__ __launch_bounds__(256) void sgemm128_nt(
    const float* __restrict__ A, const float* __restrict__ B,
    int M, int N, int K)
{
    float* C = g_xz;
    __shared__ __align__(16) float As[2][8][128];
    __shared__ __align__(16) float Bs[2][8][128];

    const int tid = threadIdx.x;
    const int m0 = blockIdx.y * 128;
    const int n0 = blockIdx.x * 128;

    const int lr = tid >> 1;          // 0..127
    const int lk = (tid & 1) * 4;     // 0 or 4
    const float* Ap = A + (size_t)(m0 + lr) * K + lk;
    const float* Bp = B + (size_t)(n0 + lr) * K + lk;

    const int ty = tid >> 4;          // 0..15
    const int tx = tid & 15;          // 0..15

    unsigned long long acc2[8][4];
#pragma unroll
    for (int i = 0; i < 8; i++)
#pragma unroll
        for (int j = 0; j < 4; j++) acc2[i][j] = 0ull;

    const int NT = K / 8;
    {
        float4 av = *(const float4*)(Ap);
        float4 bv = *(const float4*)(Bp);
        As[0][lk + 0][lr] = av.x; As[0][lk + 1][lr] = av.y;
        As[0][lk + 2][lr] = av.z; As[0][lk + 3][lr] = av.w;
        Bs[0][lk + 0][lr] = bv.x; Bs[0][lk + 1][lr] = bv.y;
        Bs[0][lk + 2][lr] = bv.z; Bs[0][lk + 3][lr] = bv.w;
    }
    __syncthreads();

    int buf = 0;
    for (int t = 0; t < NT; t++) {
        float4 av2, bv2;
        const bool more = (t + 1 < NT);
        if (more) {
            av2 = *(const float4*)(Ap + (t + 1) * 8);
            bv2 = *(const float4*)(Bp + (t + 1) * 8);
        }
#pragma unroll
        for (int k = 0; k < 8; k++) {
            float a[8];
            *(float4*)(a)     = *(const float4*)&As[buf][k][ty * 8];
            *(float4*)(a + 4) = *(const float4*)&As[buf][k][ty * 8 + 4];
            const double2 q0 = *(const double2*)&Bs[buf][k][tx * 8];
            const double2 q1 = *(const double2*)&Bs[buf][k][tx * 8 + 4];
            unsigned long long b2[4];
            b2[0] = __double_as_longlong(q0.x);
            b2[1] = __double_as_longlong(q0.y);
            b2[2] = __double_as_longlong(q1.x);
            b2[3] = __double_as_longlong(q1.y);
#pragma unroll
            for (int i = 0; i < 8; i++) {
                const unsigned long long ad = dupf2(a[i]);
                FMA2(acc2[i][0], ad, b2[0]);
                FMA2(acc2[i][1], ad, b2[1]);
                FMA2(acc2[i][2], ad, b2[2]);
                FMA2(acc2[i][3], ad, b2[3]);
            }
        }
        if (more) {
            const int nb = buf ^ 1;
            As[nb][lk + 0][lr] = av2.x; As[nb][lk + 1][lr] = av2.y;
            As[nb][lk + 2][lr] = av2.z; As[nb][lk + 3][lr] = av2.w;
            Bs[nb][lk + 0][lr] = bv2.x; Bs[nb][lk + 1][lr] = bv2.y;
            Bs[nb][lk + 2][lr] = bv2.z; Bs[nb][lk + 3][lr] = bv2.w;
            __syncthreads();
            buf = nb;
        }
    }

#pragma unroll
    for (int i = 0; i < 8; i++) {
        float* cp = C + (size_t)(m0 + ty * 8 + i) * N + n0 + tx * 8;
        const float2 p0 = unpack2(acc2[i][0]);
        const float2 p1 = unpack2(acc2[i][1]);
        const float2 p2 = unpack2(acc2[i][2]);
        const float2 p3 = unpack2(acc2[i][3]);
        *(float4*)(cp)     = make_float4(p0.x, p0.y, p1.x, p1.y);
        *(float4*)(cp + 4) = make_float4(p2.x, p2.y, p3.x, p3.y);
    }
}

// ---------------------------------------------------------------------------
// K6: 64m x 128n x 16k fp32 SGEMM (NT), double-buffered, f32x2 microkernel,
//     fused A = g_y[0] + g_y[1]. grid (N/128, M/64) = (6, 32) = 192 blocks.
// ---------------------------------------------------------------------------
__global__ __launch_bounds__(256) void sgemm64_out(
    const float* __restrict__ B, float* __restrict__ C, int M, int N, int K)
{
    __shared__ __align__(16) float As[2][16][64];
    __shared__ __align__(16) float Bs[2][16][128];

    const int tid = threadIdx.x;
    const int m0 = blockIdx.y * 64;
    const int n0 = blockIdx.x * 128;

    // A loaders: 64 rows x 16 k = 256 f4; thread: row = tid>>2, kf = (tid&3)*4
    const int ar = tid >> 2;
    const int ak = (tid & 3) * 4;
    const float* A0 = g_y[0] + (size_t)(m0 + ar) * K + ak;
    const float* A1 = g_y[1] + (size_t)(m0 + ar) * K + ak;
    // B loaders: 128 rows x 16 k = 512 f4; thread: row = tid>>1, kf = (tid&1)*8 (+0,+4)
    const int br_ = tid >> 1;
    const int bk = (tid & 1) * 8;
    const float* Bp = B + (size_t)(n0 + br_) * K + bk;

    const int ty = tid >> 4;          // 0..15 -> m = ty*4
    const int tx = tid & 15;          // 0..15 -> n = tx*8

    unsigned long long acc2[4][4];
#pragma unroll
    for (int i = 0; i < 4; i++)
#pragma unroll
        for (int j = 0; j < 4; j++) acc2[i][j] = 0ull;

    const int NT = K / 16;

    // prologue load tile 0
    {
        float4 av = *(const float4*)(A0);
        float4 a2 = *(const float4*)(A1);
        av.x += a2.x; av.y += a2.y; av.z += a2.z; av.w += a2.w;
        As[0][ak + 0][ar] = av.x; As[0][ak + 1][ar] = av.y;
        As[0][ak + 2][ar] = av.z; As[0][ak + 3][ar] = av.w;
        float4 b0 = *(const float4*)(Bp);
        float4 b1 = *(const float4*)(Bp + 4);
        Bs[0][bk + 0][br_] = b0.x; Bs[0][bk + 1][br_] = b0.y;
        Bs[0][bk + 2][br_] = b0.z; Bs[0][bk + 3][br_] = b0.w;
        Bs[0][bk + 4][br_] = b1.x; Bs[0][bk + 5][br_] = b1.y;
        Bs[0][bk + 6][br_] = b1.z; Bs[0][bk + 7][br_] = b1.w;
    }
    __syncthreads();

    int buf = 0;
    for (int t = 0; t < NT; t++) {
        float4 avn, b0n, b1n;
        const bool more = (t + 1 < NT);
        if (more) {
            const int kt = (t + 1) * 16;
            avn = *(const float4*)(A0 + kt);
            float4 a2 = *(const float4*)(A1 + kt);
            avn.x += a2.x; avn.y += a2.y; avn.z += a2.z; avn.w += a2.w;
            b0n = *(const float4*)(Bp + kt);
            b1n = *(const float4*)(Bp + kt + 4);
        }
#pragma unroll
        for (int k = 0; k < 16; k++) {
            float a[4];
            *(float4*)(a) = *(const float4*)&As[buf][k][ty * 4];
            const double2 q0 = *(const double2*)&Bs[buf][k][tx * 8];
            const double2 q1 = *(const double2*)&Bs[buf][k][tx * 8 + 4];
            unsigned long long b2[4];
            b2[0] = __double_as_longlong(q0.x);
            b2[1] = __double_as_longlong(q0.y);
            b2[2] = __double_as_longlong(q1.x);
            b2[3] = __double_as_longlong(q1.y);
#pragma unroll
            for (int i = 0; i < 4; i++) {
                const unsigned long long ad = dupf2(a[i]);
                FMA2(acc2[i][0], ad, b2[0]);
                FMA2(acc2[i][1], ad, b2[1]);
                FMA2(acc2[i][2], ad, b2[2]);
                FMA2(acc2[i][3], ad, b2[3]);
            }
        }
        if (more) {
            const int nb = buf ^ 1;
            As[nb][ak + 0][ar] = avn.x; As[nb][ak + 1][ar] = avn.y;
            As[nb][ak + 2][ar] = avn.z; As[nb][ak + 3][ar] = avn.w;
            Bs[nb][bk + 0][br_] = b0n.x; Bs[nb][bk + 1][br_] = b0n.y;
            Bs[nb][bk + 2][br_] = b0n.z; Bs[nb][bk + 3][br_] = b0n.w;
            Bs[nb][bk + 4][br_] = b1n.x; Bs[nb][bk + 5][br_] = b1n.y;
            Bs[nb][bk + 6][br_] = b1n.z; Bs[nb][bk + 7][br_] = b1n.w;
            __syncthreads();
            buf = nb;
        }
    }

#pragma unroll
    for (int i = 0; i < 4; i++) {
        float* cp = C + (size_t)(m0 + ty * 4 + i) * N + n0 + tx * 8;
        const float2 p0 = unpack2(acc2[i][0]);
        const float2 p1 = unpack2(acc2[i][1]);
        const float2 p2 = unpack2(acc2[i][2]);
        const float2 p3 = unpack2(acc2[i][3]);
        *(float4*)(cp)     = make_float4(p0.x, p0.y, p1.x, p1.y);
        *(float4*)(cp + 4) = make_float4(p2.x, p2.y, p3.x, p3.y);
    }
}

// ---------------------------------------------------------------------------
// K2: depthwise causal conv (K=4) + SiLU, both branches (branch 1 reversed L)
// ---------------------------------------------------------------------------
__global__ __launch_bounds__(256) void conv_silu_kernel(
    const float* __restrict__ cw_f, const float* __restrict__ cb_f,
    const float* __restrict__ cw_b, const float* __restrict__ cb_b)
{
    const int m = blockIdx.x;
    const int br = blockIdx.y;
    const int b = m >> 10;
    const int t = m & 1023;
    const float* cw = br ? cw_b : cw_f;
    const float* cb = br ? cb_b : cb_f;

    for (int d = threadIdx.x; d < DINNER; d += 256) {
        float acc = cb[d];
        float4 w = *(const float4*)(cw + d * 4);
        float wk[4] = {w.x, w.y, w.z, w.w};
#pragma unroll
        for (int k = 0; k < 4; k++) {
            int tk = t - 3 + k;
            if (tk >= 0) {
                int ls = br ? (SEQLEN - 1 - tk) : tk;
                acc = fmaf(wk[k],
                           g_xz[((size_t)b * SEQLEN + ls) * (2 * DINNER) + d], acc);
            }
        }
        float s = acc / (1.f + __expf(-acc));
        g_xc[br][(size_t)m * DINNER + d] = s;
    }
}

// ---------------------------------------------------------------------------
// K3: x_dbl = xc @ x_proj^T tiled GEMM. Block: 64m x 80n, k-tile 16.
//     grid (32, 2). micro = 4m x 5n per thread (256 threads).
// ---------------------------------------------------------------------------
__global__ __launch_bounds__(256) void xdbl_gemm(
    const float* __restrict__ xpw_f, const float* __restrict__ xpw_b)
{
    __shared__ __align__(16) float As[16][64];   // [k][m]
    __shared__ __align__(16) float Bs[16][80];   // [k][n]

    const int br = blockIdx.y;
    const int m0 = blockIdx.x * 64;
    const float* xpw = br ? xpw_b : xpw_f;
    const float* xc = g_xc[br];
    const int tid = threadIdx.x;
    const int ty = tid >> 4;       // 0..15 -> m = ty*4
    const int tx = tid & 15;       // 0..15 -> n = tx*5

    // A-load: 64 rows x 4 f4 = 256 f4 -> one per thread
    const int arow = tid >> 2;
    const int af = tid & 3;
    // B-load: 80 rows x 4 f4 = 320 f4 -> idx tid and tid+256 (tid<64)
    const int bn0 = tid >> 2, bf0 = tid & 3;
    const int bn1 = (tid + 256) >> 2, bf1 = (tid + 256) & 3;

    float acc[4][5];
#pragma unroll
    for (int i = 0; i < 4; i++)
#pragma unroll
        for (int j = 0; j < 5; j++) acc[i][j] = 0.f;

    for (int kt = 0; kt < DINNER; kt += 16) {
        float4 va = *(const float4*)(xc + (size_t)(m0 + arow) * DINNER + kt + af * 4);
        float4 vb0 = *(const float4*)(xpw + (size_t)bn0 * DINNER + kt + bf0 * 4);
        float4 vb1;
        if (tid < 64)
            vb1 = *(const float4*)(xpw + (size_t)bn1 * DINNER + kt + bf1 * 4);
        __syncthreads();
        As[af * 4 + 0][arow] = va.x; As[af * 4 + 1][arow] = va.y;
        As[af * 4 + 2][arow] = va.z; As[af * 4 + 3][arow] = va.w;
        Bs[bf0 * 4 + 0][bn0] = vb0.x; Bs[bf0 * 4 + 1][bn0] = vb0.y;
        Bs[bf0 * 4 + 2][bn0] = vb0.z; Bs[bf0 * 4 + 3][bn0] = vb0.w;
        if (tid < 64) {
            Bs[bf1 * 4 + 0][bn1] = vb1.x; Bs[bf1 * 4 + 1][bn1] = vb1.y;
            Bs[bf1 * 4 + 2][bn1] = vb1.z; Bs[bf1 * 4 + 3][bn1] = vb1.w;
        }
        __syncthreads();
#pragma unroll
        for (int k = 0; k < 16; k++) {
            float a[4];
            *(float4*)(a) = *(const float4*)&As[k][ty * 4];
#pragma unroll
            for (int j = 0; j < 5; j++) {
                const float bb = Bs[k][tx * 5 + j];
                acc[0][j] = fmaf(a[0], bb, acc[0][j]);
                acc[1][j] = fmaf(a[1], bb, acc[1][j]);
                acc[2][j] = fmaf(a[2], bb, acc[2][j]);
                acc[3][j] = fmaf(a[3], bb, acc[3][j]);
            }
        }
    }

#pragma unroll
    for (int i = 0; i < 4; i++)
#pragma unroll
        for (int j = 0; j < 5; j++)
            g_xdbl[br][(size_t)(m0 + ty * 4 + i) * XDBL + tx * 5 + j] = acc[i][j];
}

// ---------------------------------------------------------------------------
// K4: delta = softplus(DT(2048x48) @ dt_proj_w^T(1536x48) + bias).
//     K=48 resident. Block: 64m x 128n, micro 4m x 8n (f32x2). grid (12,32,2).
// ---------------------------------------------------------------------------
__global__ __launch_bounds__(256) void delta_gemm(
    const float* __restrict__ dtw_f, const float* __restrict__ dtb_f,
    const float* __restrict__ dtw_b, const float* __restrict__ dtb_b)
{
    __shared__ __align__(16) float As[48][64];    // [k][m] 12KB
    __shared__ __align__(16) float Bs[48][128];   // [k][n] 24KB

    const int br = blockIdx.z;
    const int m0 = blockIdx.y * 64;
    const int n0 = blockIdx.x * 128;
    const int tid = threadIdx.x;
    const float* dtw = br ? dtw_b : dtw_f;
    const float* dtb = br ? dtb_b : dtb_f;

    {
        const int row = tid >> 2;
        const int f0 = (tid & 3) * 3;
        const float* src = g_xdbl[br] + (size_t)(m0 + row) * XDBL;
#pragma unroll
        for (int f = f0; f < f0 + 3; f++) {
            float4 v = *(const float4*)(src + f * 4);
            As[f * 4 + 0][row] = v.x; As[f * 4 + 1][row] = v.y;
            As[f * 4 + 2][row] = v.z; As[f * 4 + 3][row] = v.w;
        }
    }
    {
        const int row = tid >> 1;
        const int f0 = (tid & 1) * 6;
        const float* src = dtw + (size_t)(n0 + row) * DTRANK;
#pragma unroll
        for (int f = f0; f < f0 + 6; f++) {
            float4 v = *(const float4*)(src + f * 4);
            Bs[f * 4 + 0][row] = v.x; Bs[f * 4 + 1][row] = v.y;
            Bs[f * 4 + 2][row] = v.z; Bs[f * 4 + 3][row] = v.w;
        }
    }
    __syncthreads();

    const int ty = tid >> 4;   // m = ty*4
    const int tx = tid & 15;   // n = tx*8
    unsigned long long acc2[4][4];
#pragma unroll
    for (int i = 0; i < 4; i++)
#pragma unroll
        for (int j = 0; j < 4; j++) acc2[i][j] = 0ull;

#pragma unroll 4
    for (int k = 0; k < 48; k++) {
        float a[4];
        *(float4*)(a) = *(const float4*)&As[k][ty * 4];
        const double2 q0 = *(const double2*)&Bs[k][tx * 8];
        const double2 q1 = *(const double2*)&Bs[k][tx * 8 + 4];
        unsigned long long b2[4];
        b2[0] = __double_as_longlong(q0.x);
        b2[1] = __double_as_longlong(q0.y);
        b2[2] = __double_as_longlong(q1.x);
        b2[3] = __double_as_longlong(q1.y);
#pragma unroll
        for (int i = 0; i < 4; i++) {
            const unsigned long long ad = dupf2(a[i]);
            FMA2(acc2[i][0], ad, b2[0]);
            FMA2(acc2[i][1], ad, b2[1]);
            FMA2(acc2[i][2], ad, b2[2]);
            FMA2(acc2[i][3], ad, b2[3]);
        }
    }

#pragma unroll
    for (int i = 0; i < 4; i++) {
        float* dst = g_delta[br] + (size_t)(m0 + ty * 4 + i) * DINNER + n0 + tx * 8;
#pragma unroll
        for (int j2 = 0; j2 < 4; j2++) {
            const float2 p = unpack2(acc2[i][j2]);
            float v0 = p.x + dtb[n0 + tx * 8 + j2 * 2];
            float v1 = p.y + dtb[n0 + tx * 8 + j2 * 2 + 1];
            dst[j2 * 2]     = (v0 > 20.f) ? v0 : log1pf(__expf(v0));
            dst[j2 * 2 + 1] = (v1 > 20.f) ? v1 : log1pf(__expf(v1));
        }
    }
}

// ---------------------------------------------------------------------------
// K5: selective scan, 16-lane group per (branch,b,d), 1-deep load pipeline.
// ---------------------------------------------------------------------------
__global__ __launch_bounds__(256) void scan_kernel(
    const float* __restrict__ Alog_f, const float* __restrict__ D_f,
    const float* __restrict__ Alog_b, const float* __restrict__ D_b)
{
    const int warp = (blockIdx.x * 256 + threadIdx.x) >> 5;
    const int lane = threadIdx.x & 31;
    const int ch = warp * 2 + (lane >> 4);     // 0..6143
    const int n = lane & 15;
    const int d = ch % DINNER;
    const int bb = ch / DINNER;                // 0..3
    const int b = bb & 1;
    const int br = bb >> 1;

    const float* Alog = br ? Alog_b : Alog_f;
    const float* Dp = br ? D_b : D_f;
    const float Acoef = -__expf(Alog[d * DSTATE + n]);
    const float Dd = Dp[d];

    const size_t base = (size_t)b * SEQLEN;
    const float* dP = g_delta[br] + base * DINNER + d;
    const float* xP = g_xc[br] + base * DINNER + d;
    const float* bP = g_xdbl[br] + base * XDBL + DTRANK + n;
    const float* cP = g_xdbl[br] + base * XDBL + DTRANK + DSTATE + n;

    const float* zP;
    float* yP;
    ptrdiff_t zs, ys;
    if (br == 0) {
        zP = g_xz + base * (2 * DINNER) + DINNER + d;
        zs = 2 * DINNER;
        yP = g_y[0] + base * DINNER + d;
        ys = DINNER;
    } else {
        zP = g_xz + (base + SEQLEN - 1) * (2 * DINNER) + DINNER + d;
        zs = -(ptrdiff_t)(2 * DINNER);
        yP = g_y[1] + (base + SEQLEN - 1) * DINNER + d;
        ys = -(ptrdiff_t)DINNER;
    }

    float dl = *dP, xv = *xP, bv = *bP, cv = *cP, zv = *zP;
    float h = 0.f;
    for (int t = 0; t < SEQLEN; t++) {
        float dl_n, xv_n, bv_n, cv_n, zv_n;
        if (t + 1 < SEQLEN) {
            dl_n = dP[DINNER];
            xv_n = xP[DINNER];
            bv_n = bP[XDBL];
            cv_n = cP[XDBL];
            zv_n = zP[zs];
        } else {
            dl_n = dl; xv_n = xv; bv_n = bv; cv_n = cv; zv_n = zv;
        }
        const float a = __expf(dl * Acoef);
        h = fmaf(a, h, dl * xv * bv);
        float yn = h * cv;
        yn += __shfl_xor_sync(0xffffffffu, yn, 1);
        yn += __shfl_xor_sync(0xffffffffu, yn, 2);
        yn += __shfl_xor_sync(0xffffffffu, yn, 4);
        yn += __shfl_xor_sync(0xffffffffu, yn, 8);
        if (n == 0) {
            float y = fmaf(xv, Dd, yn);
            y *= zv / (1.f + __expf(-zv));
            *yP = y;
        }
        dP += DINNER; xP += DINNER; bP += XDBL; cP += XDBL;
        zP += zs; yP += ys;
        dl = dl_n; xv = xv_n; bv = bv_n; cv = cv_n; zv = zv_n;
    }
}

// ---------------------------------------------------------------------------
// launch
// ---------------------------------------------------------------------------
extern "C" void kernel_launch(void* const* d_in, const int* in_sizes, int n_in,
                              void* d_out, int out_size)
{
    const float* hidden   = (const float*)d_in[0];
    const float* in_proj  = (const float*)d_in[1];
    const float* conv_w   = (const float*)d_in[2];
    const float* conv_b   = (const float*)d_in[3];
    const float* x_proj_w = (const float*)d_in[4];
    const float* dt_w     = (const float*)d_in[5];
    const float* dt_b     = (const float*)d_in[6];
    const float* A_log    = (const float*)d_in[7];
    const float* Dvec     = (const float*)d_in[8];
    const float* conv_w_b = (const float*)d_in[9];
    const float* conv_b_b = (const float*)d_in[10];
    const float* x_proj_wb= (const float*)d_in[11];
    const float* dt_w_b   = (const float*)d_in[12];
    const float* dt_b_b   = (const float*)d_in[13];
    const float* A_b_log  = (const float*)d_in[14];
    const float* D_b      = (const float*)d_in[15];
    const float* out_w    = (const float*)d_in[16];
    float* out = (float*)d_out;

    // 1) xz = hidden @ in_proj^T     (2048 x 3072, K=768)
    sgemm128_nt<<<dim3((2 * DINNER) / 128, MROWS / 128), 256>>>(
        hidden, in_proj, MROWS, 2 * DINNER, DMODEL);

    // 2) conv + silu (both branches)
    conv_silu_kernel<<<dim3(MROWS, 2), 256>>>(conv_w, conv_b, conv_w_b, conv_b_b);

    // 3) x_dbl = xc @ x_proj^T       (2048 x 80, K=1536)
    xdbl_gemm<<<dim3(MROWS / 64, 2), 256>>>(x_proj_w, x_proj_wb);

    // 4) delta = softplus(dt @ dt_proj^T + bias)   (2048 x 1536, K=48)
    delta_gemm<<<dim3(DINNER / 128, MROWS / 64, 2), 256>>>(dt_w, dt_b, dt_w_b, dt_b_b);

    // 5) selective scan (both branches), gated output into g_y[0]/g_y[1]
    scan_kernel<<<384, 256>>>(A_log, Dvec, A_b_log, D_b);

    // 6) out = (y_f + y_r) @ out_proj^T   (2048 x 768, K=1536)
    sgemm64_out<<<dim3(DMODEL / 128, MROWS / 64), 256>>>(
        out_w, out, MROWS, DMODEL, DINNER);
}

// round 7
// speedup vs baseline: 1.0222x; 1.0222x over previous
#include <cuda_runtime.h>
#include <cuda_bf16.h>
#include <cstdint>

// ---------------------------------------------------------------------------
// Problem constants
// ---------------------------------------------------------------------------
#define BATCH   2
#define SEQLEN  1024
#define DMODEL  768
#define DINNER  1536
#define DSTATE  16
#define DTRANK  48
#define XDBL    80          // DTRANK + 2*DSTATE
#define MROWS   (BATCH*SEQLEN)      // 2048

// ---------------------------------------------------------------------------
// Scratch (device globals: no runtime allocation allowed)
// ---------------------------------------------------------------------------
__device__ float g_xz[(size_t)MROWS * 2 * DINNER];        // (2048, 3072)
__device__ float g_xc[2][(size_t)MROWS * DINNER];         // conv+silu out per branch
__device__ float g_xdbl[2][(size_t)MROWS * XDBL];         // dt|B|C per branch
__device__ float g_delta[2][(size_t)MROWS * DINNER];      // softplus(dt_proj)
__device__ float g_y[2][(size_t)MROWS * DINNER];          // scan outputs (branch1 un-flipped)

// ---------------------------------------------------------------------------
// K1: 128x128x8 fp32 SGEMM (NT), double-buffered (scalar FFMA): C -> g_xz
// ---------------------------------------------------------------------------
__global__ __launch_bounds__(256) void sgemm128_nt(
    const float* __restrict__ A, const float* __restrict__ B,
    int M, int N, int K)
{
    float* C = g_xz;
    __shared__ __align__(16) float As[2][8][128];
    __shared__ __align__(16) float Bs[2][8][128];

    const int tid = threadIdx.x;
    const int m0 = blockIdx.y * 128;
    const int n0 = blockIdx.x * 128;

    const int lr = tid >> 1;          // 0..127
    const int lk = (tid & 1) * 4;     // 0 or 4
    const float* Ap = A + (size_t)(m0 + lr) * K + lk;
    const float* Bp = B + (size_t)(n0 + lr) * K + lk;

    const int ty = tid >> 4;          // 0..15
    const int tx = tid & 15;          // 0..15

    float acc[8][8];
#pragma unroll
    for (int i = 0; i < 8; i++)
#pragma unroll
        for (int j = 0; j < 8; j++) acc[i][j] = 0.f;

    const int NT = K / 8;
    {
        float4 av = *(const float4*)(Ap);
        float4 bv = *(const float4*)(Bp);
        As[0][lk + 0][lr] = av.x; As[0][lk + 1][lr] = av.y;
        As[0][lk + 2][lr] = av.z; As[0][lk + 3][lr] = av.w;
        Bs[0][lk + 0][lr] = bv.x; Bs[0][lk + 1][lr] = bv.y;
        Bs[0][lk + 2][lr] = bv.z; Bs[0][lk + 3][lr] = bv.w;
    }
    __syncthreads();

    int buf = 0;
    for (int t = 0; t < NT; t++) {
        float4 av2, bv2;
        const bool more = (t + 1 < NT);
        if (more) {
            av2 = *(const float4*)(Ap + (t + 1) * 8);
            bv2 = *(const float4*)(Bp + (t + 1) * 8);
        }
#pragma unroll
        for (int k = 0; k < 8; k++) {
            float a[8], b[8];
            *(float4*)(a)     = *(const float4*)&As[buf][k][ty * 8];
            *(float4*)(a + 4) = *(const float4*)&As[buf][k][ty * 8 + 4];
            *(float4*)(b)     = *(const float4*)&Bs[buf][k][tx * 8];
            *(float4*)(b + 4) = *(const float4*)&Bs[buf][k][tx * 8 + 4];
#pragma unroll
            for (int i = 0; i < 8; i++)
#pragma unroll
                for (int j = 0; j < 8; j++)
                    acc[i][j] = fmaf(a[i], b[j], acc[i][j]);
        }
        if (more) {
            const int nb = buf ^ 1;
            As[nb][lk + 0][lr] = av2.x; As[nb][lk + 1][lr] = av2.y;
            As[nb][lk + 2][lr] = av2.z; As[nb][lk + 3][lr] = av2.w;
            Bs[nb][lk + 0][lr] = bv2.x; Bs[nb][lk + 1][lr] = bv2.y;
            Bs[nb][lk + 2][lr] = bv2.z; Bs[nb][lk + 3][lr] = bv2.w;
            __syncthreads();
            buf = nb;
        }
    }

#pragma unroll
    for (int i = 0; i < 8; i++) {
        float* cp = C + (size_t)(m0 + ty * 8 + i) * N + n0 + tx * 8;
        *(float4*)(cp)     = make_float4(acc[i][0], acc[i][1], acc[i][2], acc[i][3]);
        *(float4*)(cp + 4) = make_float4(acc[i][4], acc[i][5], acc[i][6], acc[i][7]);
    }
}

// ---------------------------------------------------------------------------
// K2: depthwise causal conv (K=4) + SiLU, sliding window: 4 timesteps/thread.
//     grid (DINNER/256, MROWS/4, 2), block 256.
// ---------------------------------------------------------------------------
__global__ __launch_bounds__(256) void conv_silu_kernel(
    const float* __restrict__ cw_f, const float* __restrict__ cb_f,
    const float* __restrict__ cw_b, const float* __restrict__ cb_b)
{
    const int br = blockIdx.z;
    const int d = blockIdx.x * 256 + threadIdx.x;
    const int m0 = blockIdx.y * 4;            // 4 | 1024 so same batch for all 4
    const int b = m0 >> 10;
    const int t0 = m0 & 1023;

    const float* cw = br ? cw_b : cw_f;
    const float* cb = br ? cb_b : cb_f;
    const float4 w = *(const float4*)(cw + d * 4);
    const float wk[4] = {w.x, w.y, w.z, w.w};
    const float bias = cb[d];

    // window covers logical timesteps t0-3 .. t0+3
    float xwin[7];
#pragma unroll
    for (int k = 0; k < 7; k++) {
        const int tk = t0 - 3 + k;
        if (tk >= 0 && tk < SEQLEN) {
            const int ls = br ? (SEQLEN - 1 - tk) : tk;
            xwin[k] = g_xz[((size_t)b * SEQLEN + ls) * (2 * DINNER) + d];
        } else {
            xwin[k] = 0.f;
        }
    }

#pragma unroll
    for (int j = 0; j < 4; j++) {
        float acc = bias;
#pragma unroll
        for (int k = 0; k < 4; k++)
            acc = fmaf(wk[k], xwin[j + k], acc);
        const float s = acc / (1.f + __expf(-acc));
        g_xc[br][(size_t)(m0 + j) * DINNER + d] = s;
    }
}

// ---------------------------------------------------------------------------
// K3: fused x_proj + delta.
//   Phase A: xdbl[m0:m0+64, 0:80] = xc @ xpw^T (64m x 80n, k-tile 16),
//            writes g_xdbl, keeps dt columns (0:48) transposed in smem.
//   Phase B: delta[m0:m0+64, :] = softplus(dt @ dtw^T + bias), n-tiles of 128.
//   grid (MROWS/64, 2), block 256.
// ---------------------------------------------------------------------------
__global__ __launch_bounds__(256) void xproj_delta_kernel(
    const float* __restrict__ xpw_f, const float* __restrict__ xpw_b,
    const float* __restrict__ dtw_f, const float* __restrict__ dtb_f,
    const float* __restrict__ dtw_b, const float* __restrict__ dtb_b)
{
    // smem pool: XDt[48][64] (3072 f) persistent; phase A As[16][64](1024 f) +
    // Bs[16][80](1280 f) overlap phase B Bs[48][128](6144 f).
    __shared__ __align__(16) float pool[3072 + 6144];
    float* XDt  = pool;                 // [48][64]  (k-major for phase B A-frags)
    float* aAs  = pool + 3072;          // [16][64]
    float* aBs  = pool + 3072 + 1024;   // [16][80]
    float* bBs  = pool + 3072;          // [48][128]

    const int br = blockIdx.y;
    const int m0 = blockIdx.x * 64;
    const float* xpw = br ? xpw_b : xpw_f;
    const float* dtw = br ? dtw_b : dtw_f;
    const float* dtb = br ? dtb_b : dtb_f;
    const float* xc = g_xc[br];
    const int tid = threadIdx.x;
    const int ty = tid >> 4;       // 0..15
    const int tx = tid & 15;       // 0..15

    // ---------------- Phase A: 64m x 80n, micro 4m x 5n ----------------
    {
        const int arow = tid >> 2;
        const int af = tid & 3;
        const int bn0 = tid >> 2, bf0 = tid & 3;
        const int bn1 = (tid + 256) >> 2, bf1 = (tid + 256) & 3;

        float acc[4][5];
#pragma unroll
        for (int i = 0; i < 4; i++)
#pragma unroll
            for (int j = 0; j < 5; j++) acc[i][j] = 0.f;

        for (int kt = 0; kt < DINNER; kt += 16) {
            float4 va = *(const float4*)(xc + (size_t)(m0 + arow) * DINNER + kt + af * 4);
            float4 vb0 = *(const float4*)(xpw + (size_t)bn0 * DINNER + kt + bf0 * 4);
            float4 vb1;
            if (tid < 64)
                vb1 = *(const float4*)(xpw + (size_t)bn1 * DINNER + kt + bf1 * 4);
            __syncthreads();
            aAs[(af * 4 + 0) * 64 + arow] = va.x;
            aAs[(af * 4 + 1) * 64 + arow] = va.y;
            aAs[(af * 4 + 2) * 64 + arow] = va.z;
            aAs[(af * 4 + 3) * 64 + arow] = va.w;
            aBs[(bf0 * 4 + 0) * 80 + bn0] = vb0.x;
            aBs[(bf0 * 4 + 1) * 80 + bn0] = vb0.y;
            aBs[(bf0 * 4 + 2) * 80 + bn0] = vb0.z;
            aBs[(bf0 * 4 + 3) * 80 + bn0] = vb0.w;
            if (tid < 64) {
                aBs[(bf1 * 4 + 0) * 80 + bn1] = vb1.x;
                aBs[(bf1 * 4 + 1) * 80 + bn1] = vb1.y;
                aBs[(bf1 * 4 + 2) * 80 + bn1] = vb1.z;
                aBs[(bf1 * 4 + 3) * 80 + bn1] = vb1.w;
            }
            __syncthreads();
#pragma unroll
            for (int k = 0; k < 16; k++) {
                float a[4];
                *(float4*)(a) = *(const float4*)&aAs[k * 64 + ty * 4];
#pragma unroll
                for (int j = 0; j < 5; j++) {
                    const float bb = aBs[k * 80 + tx * 5 + j];
                    acc[0][j] = fmaf(a[0], bb, acc[0][j]);
                    acc[1][j] = fmaf(a[1], bb, acc[1][j]);
                    acc[2][j] = fmaf(a[2], bb, acc[2][j]);
                    acc[3][j] = fmaf(a[3], bb, acc[3][j]);
                }
            }
        }

        __syncthreads();   // aAs/aBs dead after this; bBs may overwrite
        // write results: gmem (all 80 cols) + XDt (first 48 cols, transposed)
#pragma unroll
        for (int i = 0; i < 4; i++) {
            const int m = ty * 4 + i;
#pragma unroll
            for (int j = 0; j < 5; j++) {
                const int n = tx * 5 + j;
                g_xdbl[br][(size_t)(m0 + m) * XDBL + n] = acc[i][j];
                if (n < DTRANK)
                    XDt[n * 64 + m] = acc[i][j];
            }
        }
    }
    __syncthreads();

    // ---------------- Phase B: delta 64m x 1536n, K=48, n-tile 128 -----------
    {
        const int brow = tid >> 1;            // 0..127
        const int bf0 = (tid & 1) * 6;        // 6 float4 per half-row
        for (int nt = 0; nt < DINNER / 128; nt++) {
            const int n0 = nt * 128;
            // load dtw tile [128 rows][48 k] -> bBs[k][row]
            const float* src = dtw + (size_t)(n0 + brow) * DTRANK;
#pragma unroll
            for (int f = bf0; f < bf0 + 6; f++) {
                float4 v = *(const float4*)(src + f * 4);
                bBs[(f * 4 + 0) * 128 + brow] = v.x;
                bBs[(f * 4 + 1) * 128 + brow] = v.y;
                bBs[(f * 4 + 2) * 128 + brow] = v.z;
                bBs[(f * 4 + 3) * 128 + brow] = v.w;
            }
            __syncthreads();

            float acc[4][8];
#pragma unroll
            for (int i = 0; i < 4; i++)
#pragma unroll
                for (int j = 0; j < 8; j++) acc[i][j] = 0.f;

#pragma unroll 4
            for (int k = 0; k < DTRANK; k++) {
                float a[4], b[8];
                *(float4*)(a)     = *(const float4*)&XDt[k * 64 + ty * 4];
                *(float4*)(b)     = *(const float4*)&bBs[k * 128 + tx * 8];
                *(float4*)(b + 4) = *(const float4*)&bBs[k * 128 + tx * 8 + 4];
#pragma unroll
                for (int i = 0; i < 4; i++)
#pragma unroll
                    for (int j = 0; j < 8; j++)
                        acc[i][j] = fmaf(a[i], b[j], acc[i][j]);
            }

#pragma unroll
            for (int i = 0; i < 4; i++) {
                float* dst = g_delta[br] + (size_t)(m0 + ty * 4 + i) * DINNER + n0 + tx * 8;
#pragma unroll
                for (int j = 0; j < 8; j++) {
                    float v = acc[i][j] + dtb[n0 + tx * 8 + j];
                    dst[j] = (v > 20.f) ? v : log1pf(__expf(v));
                }
            }
            __syncthreads();   // bBs reload safety for next tile
        }
    }
}

// ---------------------------------------------------------------------------
// K4: selective scan, 16-lane group per (branch,b,d), 1-deep load pipeline.
//     z loaded only by lane n==0; unroll 2 to interleave reduction chains.
// ---------------------------------------------------------------------------
__global__ __launch_bounds__(256) void scan_kernel(
    const float* __restrict__ Alog_f, const float* __restrict__ D_f,
    const float* __restrict__ Alog_b, const float* __restrict__ D_b)
{
    const int warp = (blockIdx.x * 256 + threadIdx.x) >> 5;
    const int lane = threadIdx.x & 31;
    const int ch = warp * 2 + (lane >> 4);     // 0..6143
    const int n = lane & 15;
    const int d = ch % DINNER;
    const int bb = ch / DINNER;                // 0..3
    const int b = bb & 1;
    const int br = bb >> 1;

    const float* Alog = br ? Alog_b : Alog_f;
    const float* Dp = br ? D_b : D_f;
    const float Acoef = -__expf(Alog[d * DSTATE + n]);
    const float Dd = Dp[d];

    const size_t base = (size_t)b * SEQLEN;
    const float* dP = g_delta[br] + base * DINNER + d;
    const float* xP = g_xc[br] + base * DINNER + d;
    const float* bP = g_xdbl[br] + base * XDBL + DTRANK + n;
    const float* cP = g_xdbl[br] + base * XDBL + DTRANK + DSTATE + n;

    const float* zP;
    float* yP;
    ptrdiff_t zs, ys;
    if (br == 0) {
        zP = g_xz + base * (2 * DINNER) + DINNER + d;
        zs = 2 * DINNER;
        yP = g_y[0] + base * DINNER + d;
        ys = DINNER;
    } else {
        zP = g_xz + (base + SEQLEN - 1) * (2 * DINNER) + DINNER + d;
        zs = -(ptrdiff_t)(2 * DINNER);
        yP = g_y[1] + (base + SEQLEN - 1) * DINNER + d;
        ys = -(ptrdiff_t)DINNER;
    }

    const bool isLane0 = (n == 0);
    float dl = *dP, xv = *xP, bv = *bP, cv = *cP;
    float zv = isLane0 ? *zP : 0.f;
    float h = 0.f;
#pragma unroll 2
    for (int t = 0; t < SEQLEN; t++) {
        float dl_n, xv_n, bv_n, cv_n, zv_n;
        if (t + 1 < SEQLEN) {
            dl_n = dP[DINNER];
            xv_n = xP[DINNER];
            bv_n = bP[XDBL];
            cv_n = cP[XDBL];
            zv_n = isLane0 ? zP[zs] : 0.f;
        } else {
            dl_n = dl; xv_n = xv; bv_n = bv; cv_n = cv; zv_n = zv;
        }
        const float a = __expf(dl * Acoef);
        h = fmaf(a, h, dl * xv * bv);
        float yn = h * cv;
        yn += __shfl_xor_sync(0xffffffffu, yn, 1);
        yn += __shfl_xor_sync(0xffffffffu, yn, 2);
        yn += __shfl_xor_sync(0xffffffffu, yn, 4);
        yn += __shfl_xor_sync(0xffffffffu, yn, 8);
        if (isLane0) {
            float y = fmaf(xv, Dd, yn);
            y *= zv / (1.f + __expf(-zv));
            *yP = y;
        }
        dP += DINNER; xP += DINNER; bP += XDBL; cP += XDBL;
        zP += zs; yP += ys;
        dl = dl_n; xv = xv_n; bv = bv_n; cv = cv_n; zv = zv_n;
    }
}

// ---------------------------------------------------------------------------
// K5: 64x64x16 fp32 SGEMM (NT), double-buffered, fused A = g_y[0] + g_y[1]
// ---------------------------------------------------------------------------
__global__ __launch_bounds__(256) void sgemm64_out(
    const float* __restrict__ B, float* __restrict__ C, int M, int N, int K)
{
    __shared__ __align__(16) float As[2][16][64];
    __shared__ __align__(16) float Bs[2][16][64];

    const int tid = threadIdx.x;
    const int m0 = blockIdx.y * 64;
    const int n0 = blockIdx.x * 64;

    const int lr = tid >> 2;          // 0..63
    const int lk = (tid & 3) * 4;     // 0,4,8,12
    const float* A0 = g_y[0] + (size_t)(m0 + lr) * K + lk;
    const float* A1 = g_y[1] + (size_t)(m0 + lr) * K + lk;
    const float* Bp = B + (size_t)(n0 + lr) * K + lk;

    const int ty = tid >> 4;          // 0..15
    const int tx = tid & 15;          // 0..15

    float acc[4][4];
#pragma unroll
    for (int i = 0; i < 4; i++)
#pragma unroll
        for (int j = 0; j < 4; j++) acc[i][j] = 0.f;

    const int NT = K / 16;
    {
        float4 av = *(const float4*)(A0);
        float4 a2 = *(const float4*)(A1);
        av.x += a2.x; av.y += a2.y; av.z += a2.z; av.w += a2.w;
        float4 bv = *(const float4*)(Bp);
        As[0][lk + 0][lr] = av.x; As[0][lk + 1][lr] = av.y;
        As[0][lk + 2][lr] = av.z; As[0][lk + 3][lr] = av.w;
        Bs[0][lk + 0][lr] = bv.x; Bs[0][lk + 1][lr] = bv.y;
        Bs[0][lk + 2][lr] = bv.z; Bs[0][lk + 3][lr] = bv.w;
    }
    __syncthreads();

    int buf = 0;
    for (int t = 0; t < NT; t++) {
        float4 av2, bv2;
        const bool more = (t + 1 < NT);
        if (more) {
            const int kt = (t + 1) * 16;
            av2 = *(const float4*)(A0 + kt);
            float4 a2 = *(const float4*)(A1 + kt);
            av2.x += a2.x; av2.y += a2.y; av2.z += a2.z; av2.w += a2.w;
            bv2 = *(const float4*)(Bp + kt);
        }
#pragma unroll
        for (int k = 0; k < 16; k++) {
            float4 a = *(const float4*)&As[buf][k][ty * 4];
            float4 b = *(const float4*)&Bs[buf][k][tx * 4];
            acc[0][0] = fmaf(a.x, b.x, acc[0][0]);
            acc[0][1] = fmaf(a.x, b.y, acc[0][1]);
            acc[0][2] = fmaf(a.x, b.z, acc[0][2]);
            acc[0][3] = fmaf(a.x, b.w, acc[0][3]);
            acc[1][0] = fmaf(a.y, b.x, acc[1][0]);
            acc[1][1] = fmaf(a.y, b.y, acc[1][1]);
            acc[1][2] = fmaf(a.y, b.z, acc[1][2]);
            acc[1][3] = fmaf(a.y, b.w, acc[1][3]);
            acc[2][0] = fmaf(a.z, b.x, acc[2][0]);
            acc[2][1] = fmaf(a.z, b.y, acc[2][1]);
            acc[2][2] = fmaf(a.z, b.z, acc[2][2]);
            acc[2][3] = fmaf(a.z, b.w, acc[2][3]);
            acc[3][0] = fmaf(a.w, b.x, acc[3][0]);
            acc[3][1] = fmaf(a.w, b.y, acc[3][1]);
            acc[3][2] = fmaf(a.w, b.z, acc[3][2]);
            acc[3][3] = fmaf(a.w, b.w, acc[3][3]);
        }
        if (more) {
            const int nb = buf ^ 1;
            As[nb][lk + 0][lr] = av2.x; As[nb][lk + 1][lr] = av2.y;
            As[nb][lk + 2][lr] = av2.z; As[nb][lk + 3][lr] = av2.w;
            Bs[nb][lk + 0][lr] = bv2.x; Bs[nb][lk + 1][lr] = bv2.y;
            Bs[nb][lk + 2][lr] = bv2.z; Bs[nb][lk + 3][lr] = bv2.w;
            __syncthreads();
            buf = nb;
        }
    }

#pragma unroll
    for (int i = 0; i < 4; i++) {
        float* cp = C + (size_t)(m0 + ty * 4 + i) * N + n0 + tx * 4;
        *(float4*)cp = make_float4(acc[i][0], acc[i][1], acc[i][2], acc[i][3]);
    }
}

// ---------------------------------------------------------------------------
// launch
// ---------------------------------------------------------------------------
extern "C" void kernel_launch(void* const* d_in, const int* in_sizes, int n_in,
                              void* d_out, int out_size)
{
    const float* hidden   = (const float*)d_in[0];
    const float* in_proj  = (const float*)d_in[1];
    const float* conv_w   = (const float*)d_in[2];
    const float* conv_b   = (const float*)d_in[3];
    const float* x_proj_w = (const float*)d_in[4];
    const float* dt_w     = (const float*)d_in[5];
    const float* dt_b     = (const float*)d_in[6];
    const float* A_log    = (const float*)d_in[7];
    const float* Dvec     = (const float*)d_in[8];
    const float* conv_w_b = (const float*)d_in[9];
    const float* conv_b_b = (const float*)d_in[10];
    const float* x_proj_wb= (const float*)d_in[11];
    const float* dt_w_b   = (const float*)d_in[12];
    const float* dt_b_b   = (const float*)d_in[13];
    const float* A_b_log  = (const float*)d_in[14];
    const float* D_b      = (const float*)d_in[15];
    const float* out_w    = (const float*)d_in[16];
    float* out = (float*)d_out;

    // 0) xz = hidden @ in_proj^T     (2048 x 3072, K=768)
    sgemm128_nt<<<dim3((2 * DINNER) / 128, MROWS / 128), 256>>>(
        hidden, in_proj, MROWS, 2 * DINNER, DMODEL);

    // 1) conv + silu (both branches), 4 timesteps per thread
    conv_silu_kernel<<<dim3(DINNER / 256, MROWS / 4, 2), 256>>>(
        conv_w, conv_b, conv_w_b, conv_b_b);

    // 2) fused x_proj + delta (both branches)
    xproj_delta_kernel<<<dim3(MROWS / 64, 2), 256>>>(
        x_proj_w, x_proj_wb, dt_w, dt_b, dt_w_b, dt_b_b);

    // 3) selective scan (both branches)  [profiled slot]
    scan_kernel<<<384, 256>>>(A_log, Dvec, A_b_log, D_b);

    // 4) out = (y_f + y_r) @ out_proj^T   (2048 x 768, K=1536)
    sgemm64_out<<<dim3(DMODEL / 64, MROWS / 64), 256>>>(
        out_w, out, MROWS, DMODEL, DINNER);
}

// round 11
// speedup vs baseline: 1.0341x; 1.0117x over previous
#include <cuda_runtime.h>
#include <cuda_bf16.h>
#include <cstdint>

// ---------------------------------------------------------------------------
// Problem constants
// ---------------------------------------------------------------------------
#define BATCH   2
#define SEQLEN  1024
#define DMODEL  768
#define DINNER  1536
#define DSTATE  16
#define DTRANK  48
#define XDBL    80          // DTRANK + 2*DSTATE
#define MROWS   (BATCH*SEQLEN)      // 2048
#define NCH     8           // scan chunks
#define CLEN    (SEQLEN/NCH)        // 128

// ---------------------------------------------------------------------------
// Scratch (device globals: no runtime allocation allowed)
// ---------------------------------------------------------------------------
__device__ float g_xz[(size_t)MROWS * 2 * DINNER];        // (2048, 3072)
__device__ float g_xc[2][(size_t)MROWS * DINNER];         // conv+silu out per branch
__device__ float g_xdbl[2][(size_t)MROWS * XDBL];         // dt|B|C per branch
__device__ float g_delta[2][(size_t)MROWS * DINNER];      // softplus(dt_proj)
__device__ float g_y[2][(size_t)MROWS * DINNER];          // scan outputs (branch1 un-flipped)
// chunked-scan intermediates: [br][b][chunk][d][n]
#define HSZ ((size_t)2 * BATCH * NCH * DINNER * DSTATE)
__device__ float g_hend[HSZ];
__device__ float g_aprod[HSZ];
__device__ float g_hstart[HSZ];

// ---------------------------------------------------------------------------
// K1: 128x128x8 fp32 SGEMM (NT), double-buffered (scalar FFMA): C -> g_xz
// ---------------------------------------------------------------------------
__global__ __launch_bounds__(256) void sgemm128_nt(
    const float* __restrict__ A, const float* __restrict__ B,
    int M, int N, int K)
{
    float* C = g_xz;
    __shared__ __align__(16) float As[2][8][128];
    __shared__ __align__(16) float Bs[2][8][128];

    const int tid = threadIdx.x;
    const int m0 = blockIdx.y * 128;
    const int n0 = blockIdx.x * 128;

    const int lr = tid >> 1;          // 0..127
    const int lk = (tid & 1) * 4;     // 0 or 4
    const float* Ap = A + (size_t)(m0 + lr) * K + lk;
    const float* Bp = B + (size_t)(n0 + lr) * K + lk;

    const int ty = tid >> 4;          // 0..15
    const int tx = tid & 15;          // 0..15

    float acc[8][8];
#pragma unroll
    for (int i = 0; i < 8; i++)
#pragma unroll
        for (int j = 0; j < 8; j++) acc[i][j] = 0.f;

    const int NT = K / 8;
    {
        float4 av = *(const float4*)(Ap);
        float4 bv = *(const float4*)(Bp);
        As[0][lk + 0][lr] = av.x; As[0][lk + 1][lr] = av.y;
        As[0][lk + 2][lr] = av.z; As[0][lk + 3][lr] = av.w;
        Bs[0][lk + 0][lr] = bv.x; Bs[0][lk + 1][lr] = bv.y;
        Bs[0][lk + 2][lr] = bv.z; Bs[0][lk + 3][lr] = bv.w;
    }
    __syncthreads();

    int buf = 0;
    for (int t = 0; t < NT; t++) {
        float4 av2, bv2;
        const bool more = (t + 1 < NT);
        if (more) {
            av2 = *(const float4*)(Ap + (t + 1) * 8);
            bv2 = *(const float4*)(Bp + (t + 1) * 8);
        }
#pragma unroll
        for (int k = 0; k < 8; k++) {
            float a[8], b[8];
            *(float4*)(a)     = *(const float4*)&As[buf][k][ty * 8];
            *(float4*)(a + 4) = *(const float4*)&As[buf][k][ty * 8 + 4];
            *(float4*)(b)     = *(const float4*)&Bs[buf][k][tx * 8];
            *(float4*)(b + 4) = *(const float4*)&Bs[buf][k][tx * 8 + 4];
#pragma unroll
            for (int i = 0; i < 8; i++)
#pragma unroll
                for (int j = 0; j < 8; j++)
                    acc[i][j] = fmaf(a[i], b[j], acc[i][j]);
        }
        if (more) {
            const int nb = buf ^ 1;
            As[nb][lk + 0][lr] = av2.x; As[nb][lk + 1][lr] = av2.y;
            As[nb][lk + 2][lr] = av2.z; As[nb][lk + 3][lr] = av2.w;
            Bs[nb][lk + 0][lr] = bv2.x; Bs[nb][lk + 1][lr] = bv2.y;
            Bs[nb][lk + 2][lr] = bv2.z; Bs[nb][lk + 3][lr] = bv2.w;
            __syncthreads();
            buf = nb;
        }
    }

#pragma unroll
    for (int i = 0; i < 8; i++) {
        float* cp = C + (size_t)(m0 + ty * 8 + i) * N + n0 + tx * 8;
        *(float4*)(cp)     = make_float4(acc[i][0], acc[i][1], acc[i][2], acc[i][3]);
        *(float4*)(cp + 4) = make_float4(acc[i][4], acc[i][5], acc[i][6], acc[i][7]);
    }
}

// ---------------------------------------------------------------------------
// K2: depthwise causal conv (K=4) + SiLU, both branches (branch 1 reversed L)
// ---------------------------------------------------------------------------
__global__ __launch_bounds__(256) void conv_silu_kernel(
    const float* __restrict__ cw_f, const float* __restrict__ cb_f,
    const float* __restrict__ cw_b, const float* __restrict__ cb_b)
{
    const int m = blockIdx.x;
    const int br = blockIdx.y;
    const int b = m >> 10;
    const int t = m & 1023;
    const float* cw = br ? cw_b : cw_f;
    const float* cb = br ? cb_b : cb_f;

    for (int d = threadIdx.x; d < DINNER; d += 256) {
        float acc = cb[d];
        float4 w = *(const float4*)(cw + d * 4);
        float wk[4] = {w.x, w.y, w.z, w.w};
#pragma unroll
        for (int k = 0; k < 4; k++) {
            int tk = t - 3 + k;
            if (tk >= 0) {
                int ls = br ? (SEQLEN - 1 - tk) : tk;
                acc = fmaf(wk[k],
                           g_xz[((size_t)b * SEQLEN + ls) * (2 * DINNER) + d], acc);
            }
        }
        float s = acc / (1.f + __expf(-acc));
        g_xc[br][(size_t)m * DINNER + d] = s;
    }
}

// ---------------------------------------------------------------------------
// K3: x_dbl = xc @ x_proj^T tiled GEMM. Block: 64m x 80n, k-tile 16.
// ---------------------------------------------------------------------------
__global__ __launch_bounds__(256) void xdbl_gemm(
    const float* __restrict__ xpw_f, const float* __restrict__ xpw_b)
{
    __shared__ __align__(16) float As[16][64];   // [k][m]
    __shared__ __align__(16) float Bs[16][80];   // [k][n]

    const int br = blockIdx.y;
    const int m0 = blockIdx.x * 64;
    const float* xpw = br ? xpw_b : xpw_f;
    const float* xc = g_xc[br];
    const int tid = threadIdx.x;
    const int ty = tid >> 4;       // 0..15 -> m = ty*4
    const int tx = tid & 15;       // 0..15 -> n = tx*5

    const int arow = tid >> 2;
    const int af = tid & 3;
    const int bn0 = tid >> 2, bf0 = tid & 3;
    const int bn1 = (tid + 256) >> 2, bf1 = (tid + 256) & 3;

    float acc[4][5];
#pragma unroll
    for (int i = 0; i < 4; i++)
#pragma unroll
        for (int j = 0; j < 5; j++) acc[i][j] = 0.f;

    for (int kt = 0; kt < DINNER; kt += 16) {
        float4 va = *(const float4*)(xc + (size_t)(m0 + arow) * DINNER + kt + af * 4);
        float4 vb0 = *(const float4*)(xpw + (size_t)bn0 * DINNER + kt + bf0 * 4);
        float4 vb1;
        if (tid < 64)
            vb1 = *(const float4*)(xpw + (size_t)bn1 * DINNER + kt + bf1 * 4);
        __syncthreads();
        As[af * 4 + 0][arow] = va.x; As[af * 4 + 1][arow] = va.y;
        As[af * 4 + 2][arow] = va.z; As[af * 4 + 3][arow] = va.w;
        Bs[bf0 * 4 + 0][bn0] = vb0.x; Bs[bf0 * 4 + 1][bn0] = vb0.y;
        Bs[bf0 * 4 + 2][bn0] = vb0.z; Bs[bf0 * 4 + 3][bn0] = vb0.w;
        if (tid < 64) {
            Bs[bf1 * 4 + 0][bn1] = vb1.x; Bs[bf1 * 4 + 1][bn1] = vb1.y;
            Bs[bf1 * 4 + 2][bn1] = vb1.z; Bs[bf1 * 4 + 3][bn1] = vb1.w;
        }
        __syncthreads();
#pragma unroll
        for (int k = 0; k < 16; k++) {
            float a[4];
            *(float4*)(a) = *(const float4*)&As[k][ty * 4];
#pragma unroll
            for (int j = 0; j < 5; j++) {
                const float bb = Bs[k][tx * 5 + j];
                acc[0][j] = fmaf(a[0], bb, acc[0][j]);
                acc[1][j] = fmaf(a[1], bb, acc[1][j]);
                acc[2][j] = fmaf(a[2], bb, acc[2][j]);
                acc[3][j] = fmaf(a[3], bb, acc[3][j]);
            }
        }
    }

#pragma unroll
    for (int i = 0; i < 4; i++)
#pragma unroll
        for (int j = 0; j < 5; j++)
            g_xdbl[br][(size_t)(m0 + ty * 4 + i) * XDBL + tx * 5 + j] = acc[i][j];
}

// ---------------------------------------------------------------------------
// K4: delta = softplus(DT @ dt_proj_w^T + bias). Block 64m x 128n, K=48.
// ---------------------------------------------------------------------------
__global__ __launch_bounds__(256) void delta_gemm(
    const float* __restrict__ dtw_f, const float* __restrict__ dtb_f,
    const float* __restrict__ dtw_b, const float* __restrict__ dtb_b)
{
    __shared__ __align__(16) float As[48][64];    // [k][m] 12KB
    __shared__ __align__(16) float Bs[48][128];   // [k][n] 24KB

    const int br = blockIdx.z;
    const int m0 = blockIdx.y * 64;
    const int n0 = blockIdx.x * 128;
    const int tid = threadIdx.x;
    const float* dtw = br ? dtw_b : dtw_f;
    const float* dtb = br ? dtb_b : dtb_f;

    {
        const int row = tid >> 2;
        const int f0 = (tid & 3) * 3;
        const float* src = g_xdbl[br] + (size_t)(m0 + row) * XDBL;
#pragma unroll
        for (int f = f0; f < f0 + 3; f++) {
            float4 v = *(const float4*)(src + f * 4);
            As[f * 4 + 0][row] = v.x; As[f * 4 + 1][row] = v.y;
            As[f * 4 + 2][row] = v.z; As[f * 4 + 3][row] = v.w;
        }
    }
    {
        const int row = tid >> 1;
        const int f0 = (tid & 1) * 6;
        const float* src = dtw + (size_t)(n0 + row) * DTRANK;
#pragma unroll
        for (int f = f0; f < f0 + 6; f++) {
            float4 v = *(const float4*)(src + f * 4);
            Bs[f * 4 + 0][row] = v.x; Bs[f * 4 + 1][row] = v.y;
            Bs[f * 4 + 2][row] = v.z; Bs[f * 4 + 3][row] = v.w;
        }
    }
    __syncthreads();

    const int ty = tid >> 4;   // m = ty*4
    const int tx = tid & 15;   // n = tx*8
    float acc[4][8];
#pragma unroll
    for (int i = 0; i < 4; i++)
#pragma unroll
        for (int j = 0; j < 8; j++) acc[i][j] = 0.f;

#pragma unroll 4
    for (int k = 0; k < 48; k++) {
        float a[4], b[8];
        *(float4*)(a)     = *(const float4*)&As[k][ty * 4];
        *(float4*)(b)     = *(const float4*)&Bs[k][tx * 8];
        *(float4*)(b + 4) = *(const float4*)&Bs[k][tx * 8 + 4];
#pragma unroll
        for (int i = 0; i < 4; i++)
#pragma unroll
            for (int j = 0; j < 8; j++)
                acc[i][j] = fmaf(a[i], b[j], acc[i][j]);
    }

#pragma unroll
    for (int i = 0; i < 4; i++) {
        float* dst = g_delta[br] + (size_t)(m0 + ty * 4 + i) * DINNER + n0 + tx * 8;
#pragma unroll
        for (int j = 0; j < 8; j++) {
            float v = acc[i][j] + dtb[n0 + tx * 8 + j];
            dst[j] = (v > 20.f) ? v : log1pf(__expf(v));
        }
    }
}

// ---------------------------------------------------------------------------
// Chunked scan helpers: group decomposition
//   group g (0..49151): d = g % DINNER; c = (g/DINNER) % NCH;
//   bb = g/(DINNER*NCH): b = bb&1, br = bb>>1.  lane n = 0..15.
// ---------------------------------------------------------------------------

// K5a: per-chunk local scan (h0 = 0): outputs h_end and aprod per (g, n).
__global__ __launch_bounds__(256) void scan_pass1(
    const float* __restrict__ Alog_f, const float* __restrict__ Alog_b)
{
    const int gid = blockIdx.x * 256 + threadIdx.x;
    const int lane = threadIdx.x & 31;
    const int g = (gid >> 5) * 2 + (lane >> 4);
    const int n = lane & 15;
    const int d = g % DINNER;
    const int c = (g / DINNER) % NCH;
    const int bb = g / (DINNER * NCH);
    const int b = bb & 1;
    const int br = bb >> 1;

    const float* Alog = br ? Alog_b : Alog_f;
    const float Acoef = -__expf(Alog[d * DSTATE + n]);

    const size_t row0 = (size_t)b * SEQLEN + (size_t)c * CLEN;
    const float* dP = g_delta[br] + row0 * DINNER + d;
    const float* xP = g_xc[br] + row0 * DINNER + d;
    const float* bP = g_xdbl[br] + row0 * XDBL + DTRANK + n;

    float h = 0.f, ap = 1.f;
#pragma unroll 4
    for (int t = 0; t < CLEN; t++) {
        const float dl = dP[(size_t)t * DINNER];
        const float xv = xP[(size_t)t * DINNER];
        const float bv = bP[(size_t)t * XDBL];
        const float a = __expf(dl * Acoef);
        h = fmaf(a, h, dl * xv * bv);
        ap *= a;
    }
    const size_t idx = (size_t)g * DSTATE + n;
    g_hend[idx] = h;
    g_aprod[idx] = ap;
}

// K5b: sequential combine across chunks -> h_start per chunk.
__global__ __launch_bounds__(256) void scan_pass2()
{
    const int gid = blockIdx.x * 256 + threadIdx.x;  // 0..98303 = (br,b,d,n)
    const int n = gid & 15;
    const int d = (gid >> 4) % DINNER;
    const int bb = gid / (DINNER * DSTATE);
    // idx(g) with g = ((bb*NCH)+c)*DINNER + d
    const size_t stride = (size_t)DINNER * DSTATE;
    size_t idx = ((size_t)bb * NCH * DINNER + d) * DSTATE + n;
    float hs = 0.f;
#pragma unroll
    for (int c = 0; c < NCH; c++) {
        g_hstart[idx] = hs;
        hs = fmaf(g_aprod[idx], hs, g_hend[idx]);
        idx += stride;
    }
}

// K5c: full scan per chunk starting from h_start; y output with gating.
__global__ __launch_bounds__(256) void scan_pass3(
    const float* __restrict__ Alog_f, const float* __restrict__ D_f,
    const float* __restrict__ Alog_b, const float* __restrict__ D_b)
{
    const int gid = blockIdx.x * 256 + threadIdx.x;
    const int lane = threadIdx.x & 31;
    const int g = (gid >> 5) * 2 + (lane >> 4);
    const int n = lane & 15;
    const int d = g % DINNER;
    const int c = (g / DINNER) % NCH;
    const int bb = g / (DINNER * NCH);
    const int b = bb & 1;
    const int br = bb >> 1;

    const float* Alog = br ? Alog_b : Alog_f;
    const float* Dp = br ? D_b : D_f;
    const float Acoef = -__expf(Alog[d * DSTATE + n]);
    const float Dd = Dp[d];

    const size_t row0 = (size_t)b * SEQLEN + (size_t)c * CLEN;
    const float* dP = g_delta[br] + row0 * DINNER + d;
    const float* xP = g_xc[br] + row0 * DINNER + d;
    const float* bP = g_xdbl[br] + row0 * XDBL + DTRANK + n;
    const float* cP = g_xdbl[br] + row0 * XDBL + DTRANK + DSTATE + n;

    // z / y pointers: logical scan step s = c*CLEN + t maps to
    //   fwd: row b*L + s ; rev: row b*L + (L-1-s)
    const float* zP;
    float* yP;
    ptrdiff_t zs, ys;
    if (br == 0) {
        zP = g_xz + row0 * (2 * DINNER) + DINNER + d;
        zs = 2 * DINNER;
        yP = g_y[0] + row0 * DINNER + d;
        ys = DINNER;
    } else {
        const size_t rrow = (size_t)b * SEQLEN + (SEQLEN - 1 - (size_t)c * CLEN);
        zP = g_xz + rrow * (2 * DINNER) + DINNER + d;
        zs = -(ptrdiff_t)(2 * DINNER);
        yP = g_y[1] + rrow * DINNER + d;
        ys = -(ptrdiff_t)DINNER;
    }

    const bool isLane0 = (n == 0);
    float h = g_hstart[(size_t)g * DSTATE + n];

    for (int t = 0; t < CLEN; t++) {
        const float dl = dP[(size_t)t * DINNER];
        const float xv = xP[(size_t)t * DINNER];
        const float bv = bP[(size_t)t * XDBL];
        const float cv = cP[(size_t)t * XDBL];
        const float a = __expf(dl * Acoef);
        h = fmaf(a, h, dl * xv * bv);
        float yn = h * cv;
        yn += __shfl_xor_sync(0xffffffffu, yn, 1);
        yn += __shfl_xor_sync(0xffffffffu, yn, 2);
        yn += __shfl_xor_sync(0xffffffffu, yn, 4);
        yn += __shfl_xor_sync(0xffffffffu, yn, 8);
        if (isLane0) {
            const float zv = zP[(ptrdiff_t)t * zs];
            float y = fmaf(xv, Dd, yn);
            y *= zv / (1.f + __expf(-zv));
            yP[(ptrdiff_t)t * ys] = y;
        }
    }
}

// ---------------------------------------------------------------------------
// K6: 64x64x16 fp32 SGEMM (NT), double-buffered, fused A = g_y[0] + g_y[1]
// ---------------------------------------------------------------------------
__global__ __launch_bounds__(256) void sgemm64_out(
    const float* __restrict__ B, float* __restrict__ C, int M, int N, int K)
{
    __shared__ __align__(16) float As[2][16][64];
    __shared__ __align__(16) float Bs[2][16][64];

    const int tid = threadIdx.x;
    const int m0 = blockIdx.y * 64;
    const int n0 = blockIdx.x * 64;

    const int lr = tid >> 2;          // 0..63
    const int lk = (tid & 3) * 4;     // 0,4,8,12
    const float* A0 = g_y[0] + (size_t)(m0 + lr) * K + lk;
    const float* A1 = g_y[1] + (size_t)(m0 + lr) * K + lk;
    const float* Bp = B + (size_t)(n0 + lr) * K + lk;

    const int ty = tid >> 4;          // 0..15
    const int tx = tid & 15;          // 0..15

    float acc[4][4];
#pragma unroll
    for (int i = 0; i < 4; i++)
#pragma unroll
        for (int j = 0; j < 4; j++) acc[i][j] = 0.f;

    const int NT = K / 16;
    {
        float4 av = *(const float4*)(A0);
        float4 a2 = *(const float4*)(A1);
        av.x += a2.x; av.y += a2.y; av.z += a2.z; av.w += a2.w;
        float4 bv = *(const float4*)(Bp);
        As[0][lk + 0][lr] = av.x; As[0][lk + 1][lr] = av.y;
        As[0][lk + 2][lr] = av.z; As[0][lk + 3][lr] = av.w;
        Bs[0][lk + 0][lr] = bv.x; Bs[0][lk + 1][lr] = bv.y;
        Bs[0][lk + 2][lr] = bv.z; Bs[0][lk + 3][lr] = bv.w;
    }
    __syncthreads();

    int buf = 0;
    for (int t = 0; t < NT; t++) {
        float4 av2, bv2;
        const bool more = (t + 1 < NT);
        if (more) {
            const int kt = (t + 1) * 16;
            av2 = *(const float4*)(A0 + kt);
            float4 a2 = *(const float4*)(A1 + kt);
            av2.x += a2.x; av2.y += a2.y; av2.z += a2.z; av2.w += a2.w;
            bv2 = *(const float4*)(Bp + kt);
        }
#pragma unroll
        for (int k = 0; k < 16; k++) {
            float4 a = *(const float4*)&As[buf][k][ty * 4];
            float4 b = *(const float4*)&Bs[buf][k][tx * 4];
            acc[0][0] = fmaf(a.x, b.x, acc[0][0]);
            acc[0][1] = fmaf(a.x, b.y, acc[0][1]);
            acc[0][2] = fmaf(a.x, b.z, acc[0][2]);
            acc[0][3] = fmaf(a.x, b.w, acc[0][3]);
            acc[1][0] = fmaf(a.y, b.x, acc[1][0]);
            acc[1][1] = fmaf(a.y, b.y, acc[1][1]);
            acc[1][2] = fmaf(a.y, b.z, acc[1][2]);
            acc[1][3] = fmaf(a.y, b.w, acc[1][3]);
            acc[2][0] = fmaf(a.z, b.x, acc[2][0]);
            acc[2][1] = fmaf(a.z, b.y, acc[2][1]);
            acc[2][2] = fmaf(a.z, b.z, acc[2][2]);
            acc[2][3] = fmaf(a.z, b.w, acc[2][3]);
            acc[3][0] = fmaf(a.w, b.x, acc[3][0]);
            acc[3][1] = fmaf(a.w, b.y, acc[3][1]);
            acc[3][2] = fmaf(a.w, b.z, acc[3][2]);
            acc[3][3] = fmaf(a.w, b.w, acc[3][3]);
        }
        if (more) {
            const int nb = buf ^ 1;
            As[nb][lk + 0][lr] = av2.x; As[nb][lk + 1][lr] = av2.y;
            As[nb][lk + 2][lr] = av2.z; As[nb][lk + 3][lr] = av2.w;
            Bs[nb][lk + 0][lr] = bv2.x; Bs[nb][lk + 1][lr] = bv2.y;
            Bs[nb][lk + 2][lr] = bv2.z; Bs[nb][lk + 3][lr] = bv2.w;
            __syncthreads();
            buf = nb;
        }
    }

#pragma unroll
    for (int i = 0; i < 4; i++) {
        float* cp = C + (size_t)(m0 + ty * 4 + i) * N + n0 + tx * 4;
        *(float4*)cp = make_float4(acc[i][0], acc[i][1], acc[i][2], acc[i][3]);
    }
}

// ---------------------------------------------------------------------------
// launch
// ---------------------------------------------------------------------------
extern "C" void kernel_launch(void* const* d_in, const int* in_sizes, int n_in,
                              void* d_out, int out_size)
{
    const float* hidden   = (const float*)d_in[0];
    const float* in_proj  = (const float*)d_in[1];
    const float* conv_w   = (const float*)d_in[2];
    const float* conv_b   = (const float*)d_in[3];
    const float* x_proj_w = (const float*)d_in[4];
    const float* dt_w     = (const float*)d_in[5];
    const float* dt_b     = (const float*)d_in[6];
    const float* A_log    = (const float*)d_in[7];
    const float* Dvec     = (const float*)d_in[8];
    const float* conv_w_b = (const float*)d_in[9];
    const float* conv_b_b = (const float*)d_in[10];
    const float* x_proj_wb= (const float*)d_in[11];
    const float* dt_w_b   = (const float*)d_in[12];
    const float* dt_b_b   = (const float*)d_in[13];
    const float* A_b_log  = (const float*)d_in[14];
    const float* D_b      = (const float*)d_in[15];
    const float* out_w    = (const float*)d_in[16];
    float* out = (float*)d_out;

    // 0) xz = hidden @ in_proj^T     (2048 x 3072, K=768)
    sgemm128_nt<<<dim3((2 * DINNER) / 128, MROWS / 128), 256>>>(
        hidden, in_proj, MROWS, 2 * DINNER, DMODEL);

    // 1) conv + silu (both branches)
    conv_silu_kernel<<<dim3(MROWS, 2), 256>>>(conv_w, conv_b, conv_w_b, conv_b_b);

    // 2) x_dbl = xc @ x_proj^T       (2048 x 80, K=1536)
    xdbl_gemm<<<dim3(MROWS / 64, 2), 256>>>(x_proj_w, x_proj_wb);

    // 3) delta = softplus(dt @ dt_proj^T + bias)
    delta_gemm<<<dim3(DINNER / 128, MROWS / 64, 2), 256>>>(dt_w, dt_b, dt_w_b, dt_b_b);

    // 4-6) chunked selective scan (both branches)
    //   groups = 2br*2b*8c*1536d = 49152; *16 lanes = 786432 thr = 3072 blocks
    scan_pass1<<<3072, 256>>>(A_log, A_b_log);
    scan_pass2<<<(2 * BATCH * DINNER * DSTATE) / 256, 256>>>();
    scan_pass3<<<3072, 256>>>(A_log, Dvec, A_b_log, D_b);

    // 7) out = (y_f + y_r) @ out_proj^T   (2048 x 768, K=1536)
    sgemm64_out<<<dim3(DMODEL / 64, MROWS / 64), 256>>>(
        out_w, out, MROWS, DMODEL, DINNER);
}

// round 12
// speedup vs baseline: 1.3734x; 1.3281x over previous
#include <cuda_runtime.h>
#include <cuda_bf16.h>
#include <cstdint>

// ---------------------------------------------------------------------------
// Problem constants
// ---------------------------------------------------------------------------
#define BATCH   2
#define SEQLEN  1024
#define DMODEL  768
#define DINNER  1536
#define DSTATE  16
#define DTRANK  48
#define XDBL    80          // DTRANK + 2*DSTATE
#define MROWS   (BATCH*SEQLEN)      // 2048
#define NCH     16          // scan chunks
#define CLEN    (SEQLEN/NCH)        // 64

// ---------------------------------------------------------------------------
// Scratch (device globals: no runtime allocation allowed)
// ---------------------------------------------------------------------------
__device__ float g_xz[(size_t)MROWS * 2 * DINNER];        // (2048, 3072)
__device__ float g_xc[2][(size_t)MROWS * DINNER];         // conv+silu out per branch
__device__ float g_xdbl[2][(size_t)MROWS * XDBL];         // dt|B|C per branch
__device__ float g_delta[2][(size_t)MROWS * DINNER];      // softplus(dt_proj)
__device__ float g_y[2][(size_t)MROWS * DINNER];          // raw scan outputs (+x*D), un-flipped
__device__ float g_ysum[(size_t)MROWS * DINNER];          // gated sum (y0+y1)*silu(z)
// chunked-scan intermediates: [br][b][chunk][d][n]
#define HSZ ((size_t)2 * BATCH * NCH * DINNER * DSTATE)
__device__ float g_hend[HSZ];
__device__ float g_aprod[HSZ];
__device__ float g_hstart[HSZ];

// ---------------------------------------------------------------------------
// K1: 128x128x8 fp32 SGEMM (NT), double-buffered (scalar FFMA): C -> g_xz
// ---------------------------------------------------------------------------
__global__ __launch_bounds__(256) void sgemm128_nt(
    const float* __restrict__ A, const float* __restrict__ B,
    int M, int N, int K)
{
    float* C = g_xz;
    __shared__ __align__(16) float As[2][8][128];
    __shared__ __align__(16) float Bs[2][8][128];

    const int tid = threadIdx.x;
    const int m0 = blockIdx.y * 128;
    const int n0 = blockIdx.x * 128;

    const int lr = tid >> 1;          // 0..127
    const int lk = (tid & 1) * 4;     // 0 or 4
    const float* Ap = A + (size_t)(m0 + lr) * K + lk;
    const float* Bp = B + (size_t)(n0 + lr) * K + lk;

    const int ty = tid >> 4;          // 0..15
    const int tx = tid & 15;          // 0..15

    float acc[8][8];
#pragma unroll
    for (int i = 0; i < 8; i++)
#pragma unroll
        for (int j = 0; j < 8; j++) acc[i][j] = 0.f;

    const int NT = K / 8;
    {
        float4 av = *(const float4*)(Ap);
        float4 bv = *(const float4*)(Bp);
        As[0][lk + 0][lr] = av.x; As[0][lk + 1][lr] = av.y;
        As[0][lk + 2][lr] = av.z; As[0][lk + 3][lr] = av.w;
        Bs[0][lk + 0][lr] = bv.x; Bs[0][lk + 1][lr] = bv.y;
        Bs[0][lk + 2][lr] = bv.z; Bs[0][lk + 3][lr] = bv.w;
    }
    __syncthreads();

    int buf = 0;
    for (int t = 0; t < NT; t++) {
        float4 av2, bv2;
        const bool more = (t + 1 < NT);
        if (more) {
            av2 = *(const float4*)(Ap + (t + 1) * 8);
            bv2 = *(const float4*)(Bp + (t + 1) * 8);
        }
#pragma unroll
        for (int k = 0; k < 8; k++) {
            float a[8], b[8];
            *(float4*)(a)     = *(const float4*)&As[buf][k][ty * 8];
            *(float4*)(a + 4) = *(const float4*)&As[buf][k][ty * 8 + 4];
            *(float4*)(b)     = *(const float4*)&Bs[buf][k][tx * 8];
            *(float4*)(b + 4) = *(const float4*)&Bs[buf][k][tx * 8 + 4];
#pragma unroll
            for (int i = 0; i < 8; i++)
#pragma unroll
                for (int j = 0; j < 8; j++)
                    acc[i][j] = fmaf(a[i], b[j], acc[i][j]);
        }
        if (more) {
            const int nb = buf ^ 1;
            As[nb][lk + 0][lr] = av2.x; As[nb][lk + 1][lr] = av2.y;
            As[nb][lk + 2][lr] = av2.z; As[nb][lk + 3][lr] = av2.w;
            Bs[nb][lk + 0][lr] = bv2.x; Bs[nb][lk + 1][lr] = bv2.y;
            Bs[nb][lk + 2][lr] = bv2.z; Bs[nb][lk + 3][lr] = bv2.w;
            __syncthreads();
            buf = nb;
        }
    }

#pragma unroll
    for (int i = 0; i < 8; i++) {
        float* cp = C + (size_t)(m0 + ty * 8 + i) * N + n0 + tx * 8;
        *(float4*)(cp)     = make_float4(acc[i][0], acc[i][1], acc[i][2], acc[i][3]);
        *(float4*)(cp + 4) = make_float4(acc[i][4], acc[i][5], acc[i][6], acc[i][7]);
    }
}

// ---------------------------------------------------------------------------
// K2: depthwise causal conv (K=4) + SiLU, both branches (branch 1 reversed L)
// ---------------------------------------------------------------------------
__global__ __launch_bounds__(256) void conv_silu_kernel(
    const float* __restrict__ cw_f, const float* __restrict__ cb_f,
    const float* __restrict__ cw_b, const float* __restrict__ cb_b)
{
    const int m = blockIdx.x;
    const int br = blockIdx.y;
    const int b = m >> 10;
    const int t = m & 1023;
    const float* cw = br ? cw_b : cw_f;
    const float* cb = br ? cb_b : cb_f;

    for (int d = threadIdx.x; d < DINNER; d += 256) {
        float acc = cb[d];
        float4 w = *(const float4*)(cw + d * 4);
        float wk[4] = {w.x, w.y, w.z, w.w};
#pragma unroll
        for (int k = 0; k < 4; k++) {
            int tk = t - 3 + k;
            if (tk >= 0) {
                int ls = br ? (SEQLEN - 1 - tk) : tk;
                acc = fmaf(wk[k],
                           g_xz[((size_t)b * SEQLEN + ls) * (2 * DINNER) + d], acc);
            }
        }
        float s = acc / (1.f + __expf(-acc));
        g_xc[br][(size_t)m * DINNER + d] = s;
    }
}

// ---------------------------------------------------------------------------
// K3: x_dbl = xc @ x_proj^T tiled GEMM. Block: 64m x 80n, k-tile 16.
// ---------------------------------------------------------------------------
__global__ __launch_bounds__(256) void xdbl_gemm(
    const float* __restrict__ xpw_f, const float* __restrict__ xpw_b)
{
    __shared__ __align__(16) float As[16][64];   // [k][m]
    __shared__ __align__(16) float Bs[16][80];   // [k][n]

    const int br = blockIdx.y;
    const int m0 = blockIdx.x * 64;
    const float* xpw = br ? xpw_b : xpw_f;
    const float* xc = g_xc[br];
    const int tid = threadIdx.x;
    const int ty = tid >> 4;       // 0..15 -> m = ty*4
    const int tx = tid & 15;       // 0..15 -> n = tx*5

    const int arow = tid >> 2;
    const int af = tid & 3;
    const int bn0 = tid >> 2, bf0 = tid & 3;
    const int bn1 = (tid + 256) >> 2, bf1 = (tid + 256) & 3;

    float acc[4][5];
#pragma unroll
    for (int i = 0; i < 4; i++)
#pragma unroll
        for (int j = 0; j < 5; j++) acc[i][j] = 0.f;

    for (int kt = 0; kt < DINNER; kt += 16) {
        float4 va = *(const float4*)(xc + (size_t)(m0 + arow) * DINNER + kt + af * 4);
        float4 vb0 = *(const float4*)(xpw + (size_t)bn0 * DINNER + kt + bf0 * 4);
        float4 vb1;
        if (tid < 64)
            vb1 = *(const float4*)(xpw + (size_t)bn1 * DINNER + kt + bf1 * 4);
        __syncthreads();
        As[af * 4 + 0][arow] = va.x; As[af * 4 + 1][arow] = va.y;
        As[af * 4 + 2][arow] = va.z; As[af * 4 + 3][arow] = va.w;
        Bs[bf0 * 4 + 0][bn0] = vb0.x; Bs[bf0 * 4 + 1][bn0] = vb0.y;
        Bs[bf0 * 4 + 2][bn0] = vb0.z; Bs[bf0 * 4 + 3][bn0] = vb0.w;
        if (tid < 64) {
            Bs[bf1 * 4 + 0][bn1] = vb1.x; Bs[bf1 * 4 + 1][bn1] = vb1.y;
            Bs[bf1 * 4 + 2][bn1] = vb1.z; Bs[bf1 * 4 + 3][bn1] = vb1.w;
        }
        __syncthreads();
#pragma unroll
        for (int k = 0; k < 16; k++) {
            float a[4];
            *(float4*)(a) = *(const float4*)&As[k][ty * 4];
#pragma unroll
            for (int j = 0; j < 5; j++) {
                const float bb = Bs[k][tx * 5 + j];
                acc[0][j] = fmaf(a[0], bb, acc[0][j]);
                acc[1][j] = fmaf(a[1], bb, acc[1][j]);
                acc[2][j] = fmaf(a[2], bb, acc[2][j]);
                acc[3][j] = fmaf(a[3], bb, acc[3][j]);
            }
        }
    }

#pragma unroll
    for (int i = 0; i < 4; i++)
#pragma unroll
        for (int j = 0; j < 5; j++)
            g_xdbl[br][(size_t)(m0 + ty * 4 + i) * XDBL + tx * 5 + j] = acc[i][j];
}

// ---------------------------------------------------------------------------
// K4: delta = softplus(DT @ dt_proj_w^T + bias). Block 64m x 128n, K=48.
// ---------------------------------------------------------------------------
__global__ __launch_bounds__(256) void delta_gemm(
    const float* __restrict__ dtw_f, const float* __restrict__ dtb_f,
    const float* __restrict__ dtw_b, const float* __restrict__ dtb_b)
{
    __shared__ __align__(16) float As[48][64];    // [k][m] 12KB
    __shared__ __align__(16) float Bs[48][128];   // [k][n] 24KB

    const int br = blockIdx.z;
    const int m0 = blockIdx.y * 64;
    const int n0 = blockIdx.x * 128;
    const int tid = threadIdx.x;
    const float* dtw = br ? dtw_b : dtw_f;
    const float* dtb = br ? dtb_b : dtb_f;

    {
        const int row = tid >> 2;
        const int f0 = (tid & 3) * 3;
        const float* src = g_xdbl[br] + (size_t)(m0 + row) * XDBL;
#pragma unroll
        for (int f = f0; f < f0 + 3; f++) {
            float4 v = *(const float4*)(src + f * 4);
            As[f * 4 + 0][row] = v.x; As[f * 4 + 1][row] = v.y;
            As[f * 4 + 2][row] = v.z; As[f * 4 + 3][row] = v.w;
        }
    }
    {
        const int row = tid >> 1;
        const int f0 = (tid & 1) * 6;
        const float* src = dtw + (size_t)(n0 + row) * DTRANK;
#pragma unroll
        for (int f = f0; f < f0 + 6; f++) {
            float4 v = *(const float4*)(src + f * 4);
            Bs[f * 4 + 0][row] = v.x; Bs[f * 4 + 1][row] = v.y;
            Bs[f * 4 + 2][row] = v.z; Bs[f * 4 + 3][row] = v.w;
        }
    }
    __syncthreads();

    const int ty = tid >> 4;   // m = ty*4
    const int tx = tid & 15;   // n = tx*8
    float acc[4][8];
#pragma unroll
    for (int i = 0; i < 4; i++)
#pragma unroll
        for (int j = 0; j < 8; j++) acc[i][j] = 0.f;

#pragma unroll 4
    for (int k = 0; k < 48; k++) {
        float a[4], b[8];
        *(float4*)(a)     = *(const float4*)&As[k][ty * 4];
        *(float4*)(b)     = *(const float4*)&Bs[k][tx * 8];
        *(float4*)(b + 4) = *(const float4*)&Bs[k][tx * 8 + 4];
#pragma unroll
        for (int i = 0; i < 4; i++)
#pragma unroll
            for (int j = 0; j < 8; j++)
                acc[i][j] = fmaf(a[i], b[j], acc[i][j]);
    }

#pragma unroll
    for (int i = 0; i < 4; i++) {
        float* dst = g_delta[br] + (size_t)(m0 + ty * 4 + i) * DINNER + n0 + tx * 8;
#pragma unroll
        for (int j = 0; j < 8; j++) {
            float v = acc[i][j] + dtb[n0 + tx * 8 + j];
            dst[j] = (v > 20.f) ? v : log1pf(__expf(v));
        }
    }
}

// ---------------------------------------------------------------------------
// Chunked scan: group g: d = g % DINNER; c = (g/DINNER) % NCH;
//   bb = g/(DINNER*NCH): b = bb&1, br = bb>>1.  lane n = 0..15.
// ---------------------------------------------------------------------------

// K5a: per-chunk local scan (h0 = 0): outputs h_end and aprod per (g, n).
__global__ __launch_bounds__(256) void scan_pass1(
    const float* __restrict__ Alog_f, const float* __restrict__ Alog_b)
{
    const int gid = blockIdx.x * 256 + threadIdx.x;
    const int lane = threadIdx.x & 31;
    const int g = (gid >> 5) * 2 + (lane >> 4);
    const int n = lane & 15;
    const int d = g % DINNER;
    const int c = (g / DINNER) % NCH;
    const int bb = g / (DINNER * NCH);
    const int b = bb & 1;
    const int br = bb >> 1;

    const float* Alog = br ? Alog_b : Alog_f;
    const float Acoef = -__expf(Alog[d * DSTATE + n]);

    const size_t row0 = (size_t)b * SEQLEN + (size_t)c * CLEN;
    const float* dP = g_delta[br] + row0 * DINNER + d;
    const float* xP = g_xc[br] + row0 * DINNER + d;
    const float* bP = g_xdbl[br] + row0 * XDBL + DTRANK + n;

    float h = 0.f, ap = 1.f;
#pragma unroll 4
    for (int t = 0; t < CLEN; t++) {
        const float dl = dP[(size_t)t * DINNER];
        const float xv = xP[(size_t)t * DINNER];
        const float bv = bP[(size_t)t * XDBL];
        const float a = __expf(dl * Acoef);
        h = fmaf(a, h, dl * xv * bv);
        ap *= a;
    }
    const size_t idx = (size_t)g * DSTATE + n;
    g_hend[idx] = h;
    g_aprod[idx] = ap;
}

// K5b: sequential combine across chunks -> h_start per chunk.
__global__ __launch_bounds__(256) void scan_pass2()
{
    const int gid = blockIdx.x * 256 + threadIdx.x;  // (br,b,d,n)
    const int n = gid & 15;
    const int d = (gid >> 4) % DINNER;
    const int bb = gid / (DINNER * DSTATE);
    const size_t stride = (size_t)DINNER * DSTATE;
    size_t idx = ((size_t)bb * NCH * DINNER + d) * DSTATE + n;
    float hs = 0.f;
#pragma unroll
    for (int c = 0; c < NCH; c++) {
        g_hstart[idx] = hs;
        hs = fmaf(g_aprod[idx], hs, g_hend[idx]);
        idx += stride;
    }
}

// K5c: full scan per chunk from h_start; stores RAW y (+x*D), no gating.
__global__ __launch_bounds__(256) void scan_pass3(
    const float* __restrict__ Alog_f, const float* __restrict__ D_f,
    const float* __restrict__ Alog_b, const float* __restrict__ D_b)
{
    const int gid = blockIdx.x * 256 + threadIdx.x;
    const int lane = threadIdx.x & 31;
    const int g = (gid >> 5) * 2 + (lane >> 4);
    const int n = lane & 15;
    const int d = g % DINNER;
    const int c = (g / DINNER) % NCH;
    const int bb = g / (DINNER * NCH);
    const int b = bb & 1;
    const int br = bb >> 1;

    const float* Alog = br ? Alog_b : Alog_f;
    const float* Dp = br ? D_b : D_f;
    const float Acoef = -__expf(Alog[d * DSTATE + n]);
    const float Dd = Dp[d];

    const size_t row0 = (size_t)b * SEQLEN + (size_t)c * CLEN;
    const float* dP = g_delta[br] + row0 * DINNER + d;
    const float* xP = g_xc[br] + row0 * DINNER + d;
    const float* bP = g_xdbl[br] + row0 * XDBL + DTRANK + n;
    const float* cP = g_xdbl[br] + row0 * XDBL + DTRANK + DSTATE + n;

    // y pointer: logical step s = c*CLEN + t ; fwd row = b*L+s, rev = b*L+(L-1-s)
    float* yP;
    ptrdiff_t ys;
    if (br == 0) {
        yP = g_y[0] + row0 * DINNER + d;
        ys = DINNER;
    } else {
        const size_t rrow = (size_t)b * SEQLEN + (SEQLEN - 1 - (size_t)c * CLEN);
        yP = g_y[1] + rrow * DINNER + d;
        ys = -(ptrdiff_t)DINNER;
    }

    const bool isLane0 = (n == 0);
    float h = g_hstart[(size_t)g * DSTATE + n];

#pragma unroll 2
    for (int t = 0; t < CLEN; t++) {
        const float dl = dP[(size_t)t * DINNER];
        const float xv = xP[(size_t)t * DINNER];
        const float bv = bP[(size_t)t * XDBL];
        const float cv = cP[(size_t)t * XDBL];
        const float a = __expf(dl * Acoef);
        h = fmaf(a, h, dl * xv * bv);
        float yn = h * cv;
        yn += __shfl_xor_sync(0xffffffffu, yn, 1);
        yn += __shfl_xor_sync(0xffffffffu, yn, 2);
        yn += __shfl_xor_sync(0xffffffffu, yn, 4);
        yn += __shfl_xor_sync(0xffffffffu, yn, 8);
        if (isLane0)
            yP[(ptrdiff_t)t * ys] = fmaf(xv, Dd, yn);
    }
}

// K5d: gated sum: ysum = (y0 + y1) * silu(z). Vectorized float4.
__global__ __launch_bounds__(256) void gate_sum_kernel()
{
    const size_t i4 = (size_t)blockIdx.x * 256 + threadIdx.x;  // float4 index
    const size_t m = i4 / (DINNER / 4);
    const size_t dc = (i4 % (DINNER / 4)) * 4;
    const float4 y0 = *(const float4*)&g_y[0][m * DINNER + dc];
    const float4 y1 = *(const float4*)&g_y[1][m * DINNER + dc];
    const float4 z  = *(const float4*)&g_xz[m * (2 * DINNER) + DINNER + dc];
    float4 o;
    o.x = (y0.x + y1.x) * (z.x / (1.f + __expf(-z.x)));
    o.y = (y0.y + y1.y) * (z.y / (1.f + __expf(-z.y)));
    o.z = (y0.z + y1.z) * (z.z / (1.f + __expf(-z.z)));
    o.w = (y0.w + y1.w) * (z.w / (1.f + __expf(-z.w)));
    *(float4*)&g_ysum[m * DINNER + dc] = o;
}

// ---------------------------------------------------------------------------
// K6: 64x64x16 fp32 SGEMM (NT), double-buffered, A = g_ysum
// ---------------------------------------------------------------------------
__global__ __launch_bounds__(256) void sgemm64_out(
    const float* __restrict__ B, float* __restrict__ C, int M, int N, int K)
{
    __shared__ __align__(16) float As[2][16][64];
    __shared__ __align__(16) float Bs[2][16][64];

    const int tid = threadIdx.x;
    const int m0 = blockIdx.y * 64;
    const int n0 = blockIdx.x * 64;

    const int lr = tid >> 2;          // 0..63
    const int lk = (tid & 3) * 4;     // 0,4,8,12
    const float* A0 = g_ysum + (size_t)(m0 + lr) * K + lk;
    const float* Bp = B + (size_t)(n0 + lr) * K + lk;

    const int ty = tid >> 4;          // 0..15
    const int tx = tid & 15;          // 0..15

    float acc[4][4];
#pragma unroll
    for (int i = 0; i < 4; i++)
#pragma unroll
        for (int j = 0; j < 4; j++) acc[i][j] = 0.f;

    const int NT = K / 16;
    {
        float4 av = *(const float4*)(A0);
        float4 bv = *(const float4*)(Bp);
        As[0][lk + 0][lr] = av.x; As[0][lk + 1][lr] = av.y;
        As[0][lk + 2][lr] = av.z; As[0][lk + 3][lr] = av.w;
        Bs[0][lk + 0][lr] = bv.x; Bs[0][lk + 1][lr] = bv.y;
        Bs[0][lk + 2][lr] = bv.z; Bs[0][lk + 3][lr] = bv.w;
    }
    __syncthreads();

    int buf = 0;
    for (int t = 0; t < NT; t++) {
        float4 av2, bv2;
        const bool more = (t + 1 < NT);
        if (more) {
            const int kt = (t + 1) * 16;
            av2 = *(const float4*)(A0 + kt);
            bv2 = *(const float4*)(Bp + kt);
        }
#pragma unroll
        for (int k = 0; k < 16; k++) {
            float4 a = *(const float4*)&As[buf][k][ty * 4];
            float4 b = *(const float4*)&Bs[buf][k][tx * 4];
            acc[0][0] = fmaf(a.x, b.x, acc[0][0]);
            acc[0][1] = fmaf(a.x, b.y, acc[0][1]);
            acc[0][2] = fmaf(a.x, b.z, acc[0][2]);
            acc[0][3] = fmaf(a.x, b.w, acc[0][3]);
            acc[1][0] = fmaf(a.y, b.x, acc[1][0]);
            acc[1][1] = fmaf(a.y, b.y, acc[1][1]);
            acc[1][2] = fmaf(a.y, b.z, acc[1][2]);
            acc[1][3] = fmaf(a.y, b.w, acc[1][3]);
            acc[2][0] = fmaf(a.z, b.x, acc[2][0]);
            acc[2][1] = fmaf(a.z, b.y, acc[2][1]);
            acc[2][2] = fmaf(a.z, b.z, acc[2][2]);
            acc[2][3] = fmaf(a.z, b.w, acc[2][3]);
            acc[3][0] = fmaf(a.w, b.x, acc[3][0]);
            acc[3][1] = fmaf(a.w, b.y, acc[3][1]);
            acc[3][2] = fmaf(a.w, b.z, acc[3][2]);
            acc[3][3] = fmaf(a.w, b.w, acc[3][3]);
        }
        if (more) {
            const int nb = buf ^ 1;
            As[nb][lk + 0][lr] = av2.x; As[nb][lk + 1][lr] = av2.y;
            As[nb][lk + 2][lr] = av2.z; As[nb][lk + 3][lr] = av2.w;
            Bs[nb][lk + 0][lr] = bv2.x; Bs[nb][lk + 1][lr] = bv2.y;
            Bs[nb][lk + 2][lr] = bv2.z; Bs[nb][lk + 3][lr] = bv2.w;
            __syncthreads();
            buf = nb;
        }
    }

#pragma unroll
    for (int i = 0; i < 4; i++) {
        float* cp = C + (size_t)(m0 + ty * 4 + i) * N + n0 + tx * 4;
        *(float4*)cp = make_float4(acc[i][0], acc[i][1], acc[i][2], acc[i][3]);
    }
}

// ---------------------------------------------------------------------------
// launch
// ---------------------------------------------------------------------------
extern "C" void kernel_launch(void* const* d_in, const int* in_sizes, int n_in,
                              void* d_out, int out_size)
{
    const float* hidden   = (const float*)d_in[0];
    const float* in_proj  = (const float*)d_in[1];
    const float* conv_w   = (const float*)d_in[2];
    const float* conv_b   = (const float*)d_in[3];
    const float* x_proj_w = (const float*)d_in[4];
    const float* dt_w     = (const float*)d_in[5];
    const float* dt_b     = (const float*)d_in[6];
    const float* A_log    = (const float*)d_in[7];
    const float* Dvec     = (const float*)d_in[8];
    const float* conv_w_b = (const float*)d_in[9];
    const float* conv_b_b = (const float*)d_in[10];
    const float* x_proj_wb= (const float*)d_in[11];
    const float* dt_w_b   = (const float*)d_in[12];
    const float* dt_b_b   = (const float*)d_in[13];
    const float* A_b_log  = (const float*)d_in[14];
    const float* D_b      = (const float*)d_in[15];
    const float* out_w    = (const float*)d_in[16];
    float* out = (float*)d_out;

    // 0) xz = hidden @ in_proj^T     (2048 x 3072, K=768)
    sgemm128_nt<<<dim3((2 * DINNER) / 128, MROWS / 128), 256>>>(
        hidden, in_proj, MROWS, 2 * DINNER, DMODEL);

    // 1) conv + silu (both branches)
    conv_silu_kernel<<<dim3(MROWS, 2), 256>>>(conv_w, conv_b, conv_w_b, conv_b_b);

    // 2) x_dbl = xc @ x_proj^T       (2048 x 80, K=1536)
    xdbl_gemm<<<dim3(MROWS / 64, 2), 256>>>(x_proj_w, x_proj_wb);

    // 3) delta = softplus(dt @ dt_proj^T + bias)
    delta_gemm<<<dim3(DINNER / 128, MROWS / 64, 2), 256>>>(dt_w, dt_b, dt_w_b, dt_b_b);

    // 4-6) chunked selective scan, NCH=16
    //   groups = 2br*2b*16c*1536d = 98304; *16 lanes = 1572864 thr = 6144 blocks
    scan_pass1<<<6144, 256>>>(A_log, A_b_log);
    scan_pass2<<<(2 * BATCH * DINNER * DSTATE) / 256, 256>>>();
    scan_pass3<<<6144, 256>>>(A_log, Dvec, A_b_log, D_b);

    // 7) gated sum: (y0+y1)*silu(z)
    gate_sum_kernel<<<(MROWS * DINNER / 4) / 256, 256>>>();

    // 8) out = ysum @ out_proj^T   (2048 x 768, K=1536)
    sgemm64_out<<<dim3(DMODEL / 64, MROWS / 64), 256>>>(
        out_w, out, MROWS, DMODEL, DINNER);
}